// round 9
// baseline (speedup 1.0000x reference)
#include <cuda_runtime.h>
#include <cstdint>
#include <math.h>

// Problem dims: B=2, S=2048, D=2048, H=16, DH=128, DFF=8192
#define BSD 8388608
#define BSF 33554432

// ---------------- scratch -------------------------------------------------
__device__ float g_xn[BSD];         // LN out (k-permuted along D)
__device__ float g_qkv[25165824];   // [4096][6144] q|k|v (logical layout)
__device__ float g_attn[BSD];       // flash out (k-permuted along D)
__device__ float g_x1[BSD];
__device__ float g_h[BSF];          // gelu out (k-permuted along DFF)
__device__ float g_wqkvt[12582912]; // [6144][2048] transposed+rounded+permuted
__device__ float g_wot[4194304];
__device__ float g_wint[16777216];
__device__ float g_woutt[16777216];
__device__ float g_bqkv[6144];

// ---------------- helpers -------------------------------------------------
__device__ __forceinline__ float to_tf32(float x) {
    float r; asm("cvt.rna.tf32.f32 %0, %1;" : "=f"(r) : "f"(x)); return r;
}
__device__ __forceinline__ uint32_t smem_u32(const void* p) {
    uint32_t a;
    asm("{ .reg .u64 t; cvta.to.shared.u64 t, %1; cvt.u32.u64 %0, t; }"
        : "=r"(a) : "l"(p));
    return a;
}
__device__ __forceinline__ void cp16(uint32_t s, const void* g) {
    asm volatile("cp.async.cg.shared.global [%0], [%1], 16;" :: "r"(s), "l"(g));
}
__device__ __forceinline__ void mma8(float* d, const uint32_t* a, const uint32_t* b) {
    asm volatile(
        "mma.sync.aligned.m16n8k8.row.col.f32.tf32.tf32.f32 "
        "{%0,%1,%2,%3}, {%4,%5,%6,%7}, {%8,%9}, {%0,%1,%2,%3};\n"
        : "+f"(d[0]), "+f"(d[1]), "+f"(d[2]), "+f"(d[3])
        : "r"(a[0]), "r"(a[1]), "r"(a[2]), "r"(a[3]), "r"(b[0]), "r"(b[1]));
}
__device__ __forceinline__ float gelu_f(float v) {
    return 0.5f * v * (1.0f + erff(v * 0.70710678118654752f));
}
// t4-major k-permutation within 32-k tile: logical offset x (0..31) -> phys
// l = x&7 (within 8-group), ks = x>>3; phys = (l&3)*8 + ks*2 + (l>>2)
__device__ __forceinline__ int permc32(int x) {
    const int l = x & 7;
    return ((l & 3) << 3) | (((x >> 3) & 3) << 1) | (l >> 2);
}
// same, with ks passed explicitly (l in 0..7)
__device__ __forceinline__ int poff(int l, int ks) {
    return ((l & 3) << 3) | (ks << 1) | (l >> 2);
}

// ---------------- weight prep ---------------------------------------------
__device__ void tp_tile(const float* __restrict__ src, float* __restrict__ dst,
                        int K, int N, int t)
{
    __shared__ float tbuf[32][33];
    const int tn = N >> 5;
    const int n0 = (t % tn) << 5, k0 = (t / tn) << 5;
    const int x = threadIdx.x & 31, y = threadIdx.x >> 5;
    #pragma unroll
    for (int i = 0; i < 32; i += 8)
        tbuf[y + i][x] = src[(size_t)(k0 + y + i) * N + n0 + x];
    __syncthreads();
    const int kp = k0 + permc32(x);
    #pragma unroll
    for (int i = 0; i < 32; i += 8)
        dst[(size_t)(n0 + y + i) * K + kp] = to_tf32(tbuf[x][y + i]);
}

__global__ __launch_bounds__(256) void prep_a(
    const float* __restrict__ wq, const float* __restrict__ wk,
    const float* __restrict__ wv, const float* __restrict__ bq,
    const float* __restrict__ bk, const float* __restrict__ bv)
{
    const int blk = blockIdx.x;
    if (blk < 12288) {
        const int w = blk >> 12, t = blk & 4095;
        const float* src = (w == 0) ? wq : (w == 1) ? wk : wv;
        tp_tile(src, g_wqkvt + (size_t)w * 4194304, 2048, 2048, t);
    } else {
        const int idx = ((blk - 12288) << 8) + threadIdx.x;
        if (idx < 6144) {
            const int sel = idx >> 11;
            const float* b = (sel == 0) ? bq : (sel == 1) ? bk : bv;
            g_bqkv[idx] = b[idx & 2047];
        }
    }
}

__global__ __launch_bounds__(256) void prep_b(
    const float* __restrict__ wo, const float* __restrict__ w_in,
    const float* __restrict__ w_out)
{
    const int blk = blockIdx.x;
    if (blk < 4096)        tp_tile(wo,    g_wot,   2048, 2048, blk);
    else if (blk < 20480)  tp_tile(w_in,  g_wint,  2048, 8192, blk - 4096);
    else                   tp_tile(w_out, g_woutt, 8192, 2048, blk - 20480);
}

// ---------------- block reduce --------------------------------------------
__device__ __forceinline__ float block_sum256(float v) {
    __shared__ float red[8];
    #pragma unroll
    for (int o = 16; o; o >>= 1) v += __shfl_xor_sync(0xffffffffu, v, o);
    const int w = threadIdx.x >> 5, l = threadIdx.x & 31;
    __syncthreads();
    if (l == 0) red[w] = v;
    __syncthreads();
    float t = red[l & 7];
    t += __shfl_xor_sync(0xffffffffu, t, 1);
    t += __shfl_xor_sync(0xffffffffu, t, 2);
    t += __shfl_xor_sync(0xffffffffu, t, 4);
    return t;
}

// ---------------- LayerNorm (tf32-rounded, t4-major permuted output) -------
__global__ __launch_bounds__(256) void ln_kernel(
    const float* __restrict__ x, const float* __restrict__ gw,
    const float* __restrict__ bw, float* __restrict__ y)
{
    const size_t base = (size_t)blockIdx.x * 2048;
    const int c0 = threadIdx.x << 3;
    const float4 v0 = *(const float4*)&x[base + c0];
    const float4 v1 = *(const float4*)&x[base + c0 + 4];

    float s = v0.x + v0.y + v0.z + v0.w + v1.x + v1.y + v1.z + v1.w;
    const float mean = block_sum256(s) * (1.0f / 2048.0f);

    float d[8];
    d[0] = v0.x - mean; d[1] = v0.y - mean; d[2] = v0.z - mean; d[3] = v0.w - mean;
    d[4] = v1.x - mean; d[5] = v1.y - mean; d[6] = v1.z - mean; d[7] = v1.w - mean;
    float q = 0.f;
    #pragma unroll
    for (int i = 0; i < 8; i++) q += d[i] * d[i];
    const float var = block_sum256(q) * (1.0f / 2048.0f);
    const float rs = rsqrtf(var + 1e-5f);

    const float4 g0 = *(const float4*)&gw[c0];
    const float4 g1 = *(const float4*)&gw[c0 + 4];
    const float4 b0 = *(const float4*)&bw[c0];
    const float4 b1 = *(const float4*)&bw[c0 + 4];
    const float ga[8] = {g0.x, g0.y, g0.z, g0.w, g1.x, g1.y, g1.z, g1.w};
    const float ba[8] = {b0.x, b0.y, b0.z, b0.w, b1.x, b1.y, b1.z, b1.w};

    float o[8];
    #pragma unroll
    for (int i = 0; i < 8; i++) o[i] = to_tf32(d[i] * rs * ga[i] + ba[i]);

    // t4-major: logical (i, i+4) -> phys base32 + i*8 + ks*2 + {0,1}
    const int ks = threadIdx.x & 3;
    const size_t b32 = base + ((threadIdx.x >> 2) << 5);
    #pragma unroll
    for (int i = 0; i < 4; i++)
        *(float2*)&y[b32 + (i << 3) + (ks << 1)] = make_float2(o[i], o[i + 4]);
}

// ---------------- TF32 GEMM: LDS.128 frags, pad-36 rows, 3 stages ----------
// C[M,N] = A[M,K] @ Wt[N,K]^T. A,Wt t4-major k-permuted, tf32 pre-rounded.
// CTA 128x128, K-tile 32, 8 warps 4(m)x2(n), warp 32x64.
// Stage: A 128x36f + B 128x36f = 36864B; 3 stages = 110592B.
#define GSMEM 110592

template<int ACT, int HASRES, int RND, int PERMC>
__global__ __launch_bounds__(256, 2) void gemm_cp(
    const float* __restrict__ A, const float* __restrict__ Wt,
    const float* __restrict__ bias, const float* __restrict__ res,
    float* __restrict__ C, int M, int N, int K)
{
    extern __shared__ float sm[];
    const uint32_t sb = smem_u32(sm);
    const int tid = threadIdx.x;
    const int warp = tid >> 5, lane = tid & 31;
    const int wm = warp >> 1, wn = warp & 1;
    const int g = lane >> 2, t4 = lane & 3;
    const int bm = blockIdx.y << 7, bn = blockIdx.x << 7;

    const int KT = K >> 5;

    // copy geometry: 1 smem offset + 2 running global pointers + stride
    const int r0 = tid >> 3, cc = (tid & 7) << 2;
    const uint32_t dA0 = (uint32_t)(r0 * 144 + ((tid & 7) << 4));
    const float* gA = A  + (size_t)(bm + r0) * K + cc;
    const float* gB = Wt + (size_t)(bn + r0) * K + cc;
    const size_t gstep = (size_t)K << 5;   // 32 rows

    float acc[2][8][4];
    #pragma unroll
    for (int a = 0; a < 2; a++)
        #pragma unroll
        for (int b2 = 0; b2 < 8; b2++)
            #pragma unroll
            for (int c = 0; c < 4; c++) acc[a][b2][c] = 0.f;

    auto issue = [&](int s) {
        const uint32_t st = sb + (uint32_t)s * 36864u;
        const float* ga = gA; const float* gb = gB;
        #pragma unroll
        for (int i = 0; i < 4; i++) {
            cp16(st + dA0 + i * 4608u, ga);
            cp16(st + 18432u + dA0 + i * 4608u, gb);
            ga += gstep; gb += gstep;
        }
        gA += 32; gB += 32;
        asm volatile("cp.async.commit_group;" ::: "memory");
    };

    issue(0);
    issue(1);

    const int arow0 = ((wm << 5) + g) * 36 + (t4 << 3);
    const int brow0 = ((wn << 6) + g) * 36 + (t4 << 3);

    int s = 0;
    for (int kt = 0; kt < KT; kt++) {
        if (kt + 1 < KT) asm volatile("cp.async.wait_group 1;" ::: "memory");
        else             asm volatile("cp.async.wait_group 0;" ::: "memory");
        __syncthreads();
        if (kt + 2 < KT) {
            int ns = s + 2; if (ns >= 3) ns -= 3;
            issue(ns);
        }
        const float* As = sm + s * 9216;
        const float* Bs = As + 4608;

        #pragma unroll
        for (int P = 0; P < 2; P++) {
            const float4 A00 = *(const float4*)&As[arow0 + (P << 2)];
            const float4 A01 = *(const float4*)&As[arow0 + 288 + (P << 2)];
            const float4 A10 = *(const float4*)&As[arow0 + 576 + (P << 2)];
            const float4 A11 = *(const float4*)&As[arow0 + 864 + (P << 2)];
            uint32_t af00[4] = {__float_as_uint(A00.x), __float_as_uint(A01.x),
                                __float_as_uint(A00.y), __float_as_uint(A01.y)};
            uint32_t af01[4] = {__float_as_uint(A10.x), __float_as_uint(A11.x),
                                __float_as_uint(A10.y), __float_as_uint(A11.y)};
            uint32_t af10[4] = {__float_as_uint(A00.z), __float_as_uint(A01.z),
                                __float_as_uint(A00.w), __float_as_uint(A01.w)};
            uint32_t af11[4] = {__float_as_uint(A10.z), __float_as_uint(A11.z),
                                __float_as_uint(A10.w), __float_as_uint(A11.w)};
            #pragma unroll
            for (int ni = 0; ni < 8; ni++) {
                const float4 B0 = *(const float4*)&Bs[brow0 + ni * 288 + (P << 2)];
                uint32_t bf0[2] = {__float_as_uint(B0.x), __float_as_uint(B0.y)};
                uint32_t bf1[2] = {__float_as_uint(B0.z), __float_as_uint(B0.w)};
                mma8(acc[0][ni], af00, bf0);
                mma8(acc[1][ni], af01, bf0);
                mma8(acc[0][ni], af10, bf1);
                mma8(acc[1][ni], af11, bf1);
            }
        }
        if (++s == 3) s = 0;
    }

    // epilogue
    #pragma unroll
    for (int mi = 0; mi < 2; mi++) {
        const int row0 = bm + (wm << 5) + (mi << 4) + g;
        #pragma unroll
        for (int ni = 0; ni < 8; ni++) {
            const int base = bn + (wn << 6) + (ni << 3);
            const int lcol = base + (t4 << 1);
            const float b0 = bias[lcol], b1 = bias[lcol + 1];
            float v00 = acc[mi][ni][0] + b0, v01 = acc[mi][ni][1] + b1;
            float v10 = acc[mi][ni][2] + b0, v11 = acc[mi][ni][3] + b1;
            const size_t i0 = (size_t)row0 * N + lcol;
            const size_t i1 = i0 + (size_t)8 * N;
            if (HASRES) {
                v00 += res[i0]; v01 += res[i0 + 1];
                v10 += res[i1]; v11 += res[i1 + 1];
            }
            if (ACT == 1) {
                v00 = to_tf32(gelu_f(v00)); v01 = to_tf32(gelu_f(v01));
                v10 = to_tf32(gelu_f(v10)); v11 = to_tf32(gelu_f(v11));
            } else if (RND) {
                v00 = to_tf32(v00); v01 = to_tf32(v01);
                v10 = to_tf32(v10); v11 = to_tf32(v11);
            }
            if (PERMC) {
                const int ks = ni & 3;
                const int p0 = poff(t4 << 1, ks);   // p1 = p0 + 8
                const size_t r0i = (size_t)row0 * N + (base & ~31) + p0;
                const size_t r1i = r0i + (size_t)8 * N;
                C[r0i] = v00; C[r0i + 8] = v01;
                C[r1i] = v10; C[r1i + 8] = v11;
            } else {
                *(float2*)&C[i0] = make_float2(v00, v01);
                *(float2*)&C[i1] = make_float2(v10, v11);
            }
        }
    }
}

// ---------------- causal flash attention (tf32 mma, K-tile 32, 2 CTA/SM) ---
// smem: Qs[64][132], Ks[32][132], Vs[32][132], Ss[64][36], m/l/a[64] = 77568B
#define FSMEM 77568

__global__ __launch_bounds__(256, 2) void flash_kernel(
    const float* __restrict__ QKV, float* __restrict__ O)
{
    extern __shared__ float smf[];
    float* Qs   = smf;                 // [64][132]
    float* Ks   = smf + 8448;          // [32][132]
    float* Vs   = smf + 12672;         // [32][132]
    float* Ss   = smf + 16896;         // [64][36]
    float* mrow = smf + 19200;
    float* lrow = smf + 19264;
    float* arow = smf + 19328;

    const int tid = threadIdx.x;
    const int warp = tid >> 5, lane = tid & 31;
    const int g = lane >> 2, t4 = lane & 3;
    const int wm = warp >> 1, wn = warp & 1;
    const int b = blockIdx.y >> 4, h = blockIdx.y & 15;
    const int q0 = blockIdx.x << 6;
    const size_t qbase = (size_t)b * 2048 * 6144 + (size_t)h * 128;
    const float* Qg = QKV + qbase;
    const float* Kg = QKV + qbase + 2048;
    const float* Vg = QKV + qbase + 4096;
    float*       Og = O + ((size_t)b * 2048) * 2048 + (size_t)h * 128;

    #pragma unroll
    for (int rr = 0; rr < 8; rr++) {
        const int f4 = tid + (rr << 8);
        const int row = f4 >> 5, c4 = f4 & 31;
        *(float4*)&Qs[row * 132 + (c4 << 2)] =
            *(const float4*)&Qg[(size_t)(q0 + row) * 6144 + (c4 << 2)];
    }
    if (tid < 64) { mrow[tid] = -1e30f; lrow[tid] = 0.f; }

    float o[2][4][4];
    #pragma unroll
    for (int mi = 0; mi < 2; mi++)
        #pragma unroll
        for (int ni = 0; ni < 4; ni++)
            #pragma unroll
            for (int c = 0; c < 4; c++) o[mi][ni][c] = 0.f;

    const int ntile = (q0 >> 5) + 2;
    for (int kt = 0; kt < ntile; kt++) {
        const int k0 = kt << 5;
        __syncthreads();
        #pragma unroll
        for (int rr = 0; rr < 4; rr++) {
            const int f4 = tid + (rr << 8);
            const int row = f4 >> 5, c4 = f4 & 31;
            *(float4*)&Ks[row * 132 + (c4 << 2)] =
                *(const float4*)&Kg[(size_t)(k0 + row) * 6144 + (c4 << 2)];
            *(float4*)&Vs[row * 132 + (c4 << 2)] =
                *(const float4*)&Vg[(size_t)(k0 + row) * 6144 + (c4 << 2)];
        }
        __syncthreads();

        // S[64,32] = Q K^T  (warp tile 16m x 16n)
        {
            float sacc[2][4];
            #pragma unroll
            for (int ni = 0; ni < 2; ni++)
                #pragma unroll
                for (int c = 0; c < 4; c++) sacc[ni][c] = 0.f;
            const int m0 = wm << 4;
            #pragma unroll
            for (int kk = 0; kk < 16; kk++) {
                const int kb = kk << 3;
                uint32_t af[4];
                af[0] = __float_as_uint(Qs[(m0 + g    ) * 132 + kb + t4    ]);
                af[1] = __float_as_uint(Qs[(m0 + g + 8) * 132 + kb + t4    ]);
                af[2] = __float_as_uint(Qs[(m0 + g    ) * 132 + kb + t4 + 4]);
                af[3] = __float_as_uint(Qs[(m0 + g + 8) * 132 + kb + t4 + 4]);
                #pragma unroll
                for (int ni = 0; ni < 2; ni++) {
                    const int n = (wn << 4) + (ni << 3) + g;
                    uint32_t bf[2];
                    bf[0] = __float_as_uint(Ks[n * 132 + kb + t4    ]);
                    bf[1] = __float_as_uint(Ks[n * 132 + kb + t4 + 4]);
                    mma8(sacc[ni], af, bf);
                }
            }
            #pragma unroll
            for (int ni = 0; ni < 2; ni++) {
                const int col = (wn << 4) + (ni << 3) + (t4 << 1);
                const int r0 = (wm << 4) + g, r1 = r0 + 8;
                float v00 = sacc[ni][0] * 0.08838834764831845f;
                float v01 = sacc[ni][1] * 0.08838834764831845f;
                float v10 = sacc[ni][2] * 0.08838834764831845f;
                float v11 = sacc[ni][3] * 0.08838834764831845f;
                if (k0 + col     > q0 + r0) v00 = -1e30f;
                if (k0 + col + 1 > q0 + r0) v01 = -1e30f;
                if (k0 + col     > q0 + r1) v10 = -1e30f;
                if (k0 + col + 1 > q0 + r1) v11 = -1e30f;
                Ss[r0 * 36 + col] = v00; Ss[r0 * 36 + col + 1] = v01;
                Ss[r1 * 36 + col] = v10; Ss[r1 * 36 + col + 1] = v11;
            }
        }
        __syncthreads();

        // online softmax over 32 cols; P tf32-rounded
        {
            const int rid = tid >> 2, c0 = tid & 3;
            float mx = -1e30f;
            #pragma unroll
            for (int jc = c0; jc < 32; jc += 4) mx = fmaxf(mx, Ss[rid * 36 + jc]);
            mx = fmaxf(mx, __shfl_xor_sync(0xffffffffu, mx, 1));
            mx = fmaxf(mx, __shfl_xor_sync(0xffffffffu, mx, 2));
            const float mold = mrow[rid];
            const float mnew = fmaxf(mold, mx);
            float sum = 0.f;
            #pragma unroll
            for (int jc = c0; jc < 32; jc += 4) {
                const float p = to_tf32(__expf(Ss[rid * 36 + jc] - mnew));
                Ss[rid * 36 + jc] = p;
                sum += p;
            }
            sum += __shfl_xor_sync(0xffffffffu, sum, 1);
            sum += __shfl_xor_sync(0xffffffffu, sum, 2);
            if (c0 == 0) {
                arow[rid] = __expf(mold - mnew);
                lrow[rid] = lrow[rid] * arow[rid] + sum;
                mrow[rid] = mnew;
            }
        }
        __syncthreads();

        // O^T[128,64] += V^T[128,32] @ P^T[32,64]  (warp 32d x 32q)
        {
            const int d0 = wm << 5, qw = wn << 5;
            #pragma unroll
            for (int ni = 0; ni < 4; ni++) {
                const int cq = qw + (ni << 3) + (t4 << 1);
                const float a0 = arow[cq], a1 = arow[cq + 1];
                #pragma unroll
                for (int mi = 0; mi < 2; mi++) {
                    o[mi][ni][0] *= a0; o[mi][ni][1] *= a1;
                    o[mi][ni][2] *= a0; o[mi][ni][3] *= a1;
                }
            }
            #pragma unroll
            for (int k_ = 0; k_ < 4; k_++) {
                const int kb = k_ << 3;
                uint32_t af[2][4];
                #pragma unroll
                for (int mi = 0; mi < 2; mi++) {
                    const int dm = d0 + (mi << 4);
                    af[mi][0] = __float_as_uint(Vs[(kb + t4    ) * 132 + dm + g    ]);
                    af[mi][1] = __float_as_uint(Vs[(kb + t4    ) * 132 + dm + g + 8]);
                    af[mi][2] = __float_as_uint(Vs[(kb + t4 + 4) * 132 + dm + g    ]);
                    af[mi][3] = __float_as_uint(Vs[(kb + t4 + 4) * 132 + dm + g + 8]);
                }
                #pragma unroll
                for (int ni = 0; ni < 4; ni++) {
                    const int nq = qw + (ni << 3) + g;
                    uint32_t bf[2];
                    bf[0] = __float_as_uint(Ss[nq * 36 + kb + t4    ]);
                    bf[1] = __float_as_uint(Ss[nq * 36 + kb + t4 + 4]);
                    mma8(o[0][ni], af[0], bf);
                    mma8(o[1][ni], af[1], bf);
                }
            }
        }
    }

    // normalize + store O[q][d], d permuted (t4-major) for oproj GEMM A
    __syncthreads();
    {
        const int d0 = wm << 5, qw = wn << 5;
        #pragma unroll
        for (int mi = 0; mi < 2; mi++) {
            const int pd1 = d0 + poff(g, (mi << 1));       // logical d0+mi*16+g
            const int pd2 = d0 + poff(g, (mi << 1) + 1);   // logical +8
            #pragma unroll
            for (int ni = 0; ni < 4; ni++) {
                const int cq = qw + (ni << 3) + (t4 << 1);
                const float inv0 = 1.0f / lrow[cq], inv1 = 1.0f / lrow[cq + 1];
                Og[(size_t)(q0 + cq    ) * 2048 + pd1] = to_tf32(o[mi][ni][0] * inv0);
                Og[(size_t)(q0 + cq + 1) * 2048 + pd1] = to_tf32(o[mi][ni][1] * inv1);
                Og[(size_t)(q0 + cq    ) * 2048 + pd2] = to_tf32(o[mi][ni][2] * inv0);
                Og[(size_t)(q0 + cq + 1) * 2048 + pd2] = to_tf32(o[mi][ni][3] * inv1);
            }
        }
    }
}

// ---------------- host orchestration ---------------------------------------
extern "C" void kernel_launch(void* const* d_in, const int* in_sizes, int n_in,
                              void* d_out, int out_size)
{
    const float* x     = (const float*)d_in[0];
    const float* ln1_g = (const float*)d_in[2];
    const float* ln1_b = (const float*)d_in[3];
    const float* wq    = (const float*)d_in[4];
    const float* bq    = (const float*)d_in[5];
    const float* wk    = (const float*)d_in[6];
    const float* bk    = (const float*)d_in[7];
    const float* wv    = (const float*)d_in[8];
    const float* bv    = (const float*)d_in[9];
    const float* wo    = (const float*)d_in[10];
    const float* bo    = (const float*)d_in[11];
    const float* ln2_g = (const float*)d_in[12];
    const float* ln2_b = (const float*)d_in[13];
    const float* w_in  = (const float*)d_in[14];
    const float* b_in  = (const float*)d_in[15];
    const float* w_out = (const float*)d_in[16];
    const float* b_out = (const float*)d_in[17];
    float* out = (float*)d_out;

    float *xn, *qkv, *attn, *x1, *h, *wqkvt, *wot, *wint, *woutt, *bqkv;
    cudaGetSymbolAddress((void**)&xn,     g_xn);
    cudaGetSymbolAddress((void**)&qkv,    g_qkv);
    cudaGetSymbolAddress((void**)&attn,   g_attn);
    cudaGetSymbolAddress((void**)&x1,     g_x1);
    cudaGetSymbolAddress((void**)&h,      g_h);
    cudaGetSymbolAddress((void**)&wqkvt,  g_wqkvt);
    cudaGetSymbolAddress((void**)&wot,    g_wot);
    cudaGetSymbolAddress((void**)&wint,   g_wint);
    cudaGetSymbolAddress((void**)&woutt,  g_woutt);
    cudaGetSymbolAddress((void**)&bqkv,   g_bqkv);

    cudaFuncSetAttribute(flash_kernel,
                         cudaFuncAttributeMaxDynamicSharedMemorySize, FSMEM);
    cudaFuncSetAttribute(gemm_cp<0,0,1,0>,
                         cudaFuncAttributeMaxDynamicSharedMemorySize, GSMEM);
    cudaFuncSetAttribute(gemm_cp<0,1,0,0>,
                         cudaFuncAttributeMaxDynamicSharedMemorySize, GSMEM);
    cudaFuncSetAttribute(gemm_cp<1,0,0,1>,
                         cudaFuncAttributeMaxDynamicSharedMemorySize, GSMEM);

    prep_a<<<12312, 256>>>(wq, wk, wv, bq, bk, bv);                     // 1
    prep_b<<<36864, 256>>>(wo, w_in, w_out);                            // 2
    ln_kernel<<<4096, 256>>>(x, ln1_g, ln1_b, xn);                      // 3
    gemm_cp<0,0,1,0><<<dim3(48, 32), 256, GSMEM>>>(                     // 4: QKV
        xn, wqkvt, bqkv, nullptr, qkv, 4096, 6144, 2048);
    flash_kernel<<<dim3(32, 32), 256, FSMEM>>>(qkv, attn);              // 5
    gemm_cp<0,1,0,0><<<dim3(16, 32), 256, GSMEM>>>(                     // 6: O-proj
        attn, wot, bo, x, x1, 4096, 2048, 2048);
    ln_kernel<<<4096, 256>>>(x1, ln2_g, ln2_b, xn);                     // 7
    gemm_cp<1,0,0,1><<<dim3(64, 32), 256, GSMEM>>>(                     // 8: MLP in
        xn, wint, b_in, nullptr, h, 4096, 8192, 2048);
    gemm_cp<0,1,0,0><<<dim3(16, 32), 256, GSMEM>>>(                     // 9: MLP out
        h, woutt, b_out, x1, out, 4096, 2048, 8192);
}

// round 11
// speedup vs baseline: 1.1594x; 1.1594x over previous
#include <cuda_runtime.h>
#include <cstdint>
#include <math.h>

// Problem dims: B=2, S=2048, D=2048, H=16, DH=128, DFF=8192
#define BSD 8388608   // B*S*D
#define BSF 33554432  // B*S*DFF

// ---------------- scratch (static device globals; no runtime allocation) ---
__device__ float g_xn[BSD];         // LN out (k-permuted along D)
__device__ float g_qkv[25165824];   // [4096][6144] q|k|v
__device__ float g_attn[BSD];       // flash out (k-permuted along D)
__device__ float g_x1[BSD];
__device__ float g_h[BSF];          // gelu out (k-permuted along DFF)
// transposed [N,K] + tf32-rounded + k-permuted weights
__device__ float g_wqkvt[12582912]; // [6144][2048]
__device__ float g_wot[4194304];    // [2048][2048]
__device__ float g_wint[16777216];  // [8192][2048]
__device__ float g_woutt[16777216]; // [2048][8192]
__device__ float g_bqkv[6144];

// ---------------- helpers --------------------------------------------------
__device__ __forceinline__ float to_tf32(float x) {
    float r; asm("cvt.rna.tf32.f32 %0, %1;" : "=f"(r) : "f"(x)); return r;
}
__device__ __forceinline__ uint32_t smem_u32(const void* p) {
    uint32_t a;
    asm("{ .reg .u64 t; cvta.to.shared.u64 t, %1; cvt.u32.u64 %0, t; }"
        : "=r"(a) : "l"(p));
    return a;
}
__device__ __forceinline__ void cp16(uint32_t s, const void* g) {
    asm volatile("cp.async.cg.shared.global [%0], [%1], 16;" :: "r"(s), "l"(g));
}
__device__ __forceinline__ void mma8(float* d, const uint32_t* a, const uint32_t* b) {
    asm volatile(
        "mma.sync.aligned.m16n8k8.row.col.f32.tf32.tf32.f32 "
        "{%0,%1,%2,%3}, {%4,%5,%6,%7}, {%8,%9}, {%0,%1,%2,%3};\n"
        : "+f"(d[0]), "+f"(d[1]), "+f"(d[2]), "+f"(d[3])
        : "r"(a[0]), "r"(a[1]), "r"(a[2]), "r"(a[3]), "r"(b[0]), "r"(b[1]));
}
__device__ __forceinline__ float gelu_f(float v) {
    return 0.5f * v * (1.0f + erff(v * 0.70710678118654752f));
}
// fast exp via FMA-pipe poly (avoids MUFU bottleneck). x <= ~0 expected;
// very negative x (mask -1e30) clamps to ~0. rel err ~2e-6.
__device__ __forceinline__ float fexp(float x) {
    float y = x * 1.4426950408889634f;          // log2(e)
    y = fmaxf(y, -126.0f);
    const float magic = 12582912.0f;            // 1.5 * 2^23
    const float z = y + magic;
    const int   n = __float_as_int(z) - 0x4B400000;
    const float f = y - (z - magic);            // f in [-0.5, 0.5]
    float r = 0.0013333558f;
    r = fmaf(r, f, 0.0096181291f);
    r = fmaf(r, f, 0.0555041087f);
    r = fmaf(r, f, 0.2402265069f);
    r = fmaf(r, f, 0.6931471806f);
    r = fmaf(r, f, 1.0f);
    return __int_as_float(__float_as_int(r) + (n << 23));
}
// k-permutation within 8-groups: logical l -> phys (l<4 ? 2l : 2(l-4)+1)
__device__ __forceinline__ int permc(int x) {
    const int l = x & 7;
    return (x & 24) | ((l < 4) ? (l << 1) : (((l - 4) << 1) | 1));
}

// ---------------- weight prep: transpose [K,N]->[N,K], round, k-permute ----
__device__ void tp_tile(const float* __restrict__ src, float* __restrict__ dst,
                        int K, int N, int t)
{
    __shared__ float tbuf[32][33];
    const int tn = N >> 5;
    const int n0 = (t % tn) << 5, k0 = (t / tn) << 5;
    const int x = threadIdx.x & 31, y = threadIdx.x >> 5;
    #pragma unroll
    for (int i = 0; i < 32; i += 8)
        tbuf[y + i][x] = src[(size_t)(k0 + y + i) * N + n0 + x];
    __syncthreads();
    const int kp = k0 + permc(x);
    #pragma unroll
    for (int i = 0; i < 32; i += 8)
        dst[(size_t)(n0 + y + i) * K + kp] = to_tf32(tbuf[x][y + i]);
}

__global__ __launch_bounds__(256) void prep_a(
    const float* __restrict__ wq, const float* __restrict__ wk,
    const float* __restrict__ wv, const float* __restrict__ bq,
    const float* __restrict__ bk, const float* __restrict__ bv)
{
    const int blk = blockIdx.x;
    if (blk < 12288) {
        const int w = blk >> 12, t = blk & 4095;
        const float* src = (w == 0) ? wq : (w == 1) ? wk : wv;
        tp_tile(src, g_wqkvt + (size_t)w * 4194304, 2048, 2048, t);
    } else {
        const int idx = ((blk - 12288) << 8) + threadIdx.x;
        if (idx < 6144) {
            const int sel = idx >> 11;
            const float* b = (sel == 0) ? bq : (sel == 1) ? bk : bv;
            g_bqkv[idx] = b[idx & 2047];
        }
    }
}

__global__ __launch_bounds__(256) void prep_b(
    const float* __restrict__ wo, const float* __restrict__ w_in,
    const float* __restrict__ w_out)
{
    const int blk = blockIdx.x;
    if (blk < 4096)        tp_tile(wo,    g_wot,   2048, 2048, blk);
    else if (blk < 20480)  tp_tile(w_in,  g_wint,  2048, 8192, blk - 4096);
    else                   tp_tile(w_out, g_woutt, 8192, 2048, blk - 20480);
}

// ---------------- block reduce ---------------------------------------------
__device__ __forceinline__ float block_sum256(float v) {
    __shared__ float red[8];
    #pragma unroll
    for (int o = 16; o; o >>= 1) v += __shfl_xor_sync(0xffffffffu, v, o);
    const int w = threadIdx.x >> 5, l = threadIdx.x & 31;
    __syncthreads();
    if (l == 0) red[w] = v;
    __syncthreads();
    float t = red[l & 7];
    t += __shfl_xor_sync(0xffffffffu, t, 1);
    t += __shfl_xor_sync(0xffffffffu, t, 2);
    t += __shfl_xor_sync(0xffffffffu, t, 4);
    return t;
}

// ---------------- LayerNorm (tf32-rounded, k-permuted output) --------------
__global__ __launch_bounds__(256) void ln_kernel(
    const float* __restrict__ x, const float* __restrict__ gw,
    const float* __restrict__ bw, float* __restrict__ y)
{
    const size_t base = (size_t)blockIdx.x * 2048;
    const int c0 = threadIdx.x << 3;
    const float4 v0 = *(const float4*)&x[base + c0];
    const float4 v1 = *(const float4*)&x[base + c0 + 4];

    float s = v0.x + v0.y + v0.z + v0.w + v1.x + v1.y + v1.z + v1.w;
    const float mean = block_sum256(s) * (1.0f / 2048.0f);

    float d[8];
    d[0] = v0.x - mean; d[1] = v0.y - mean; d[2] = v0.z - mean; d[3] = v0.w - mean;
    d[4] = v1.x - mean; d[5] = v1.y - mean; d[6] = v1.z - mean; d[7] = v1.w - mean;
    float q = 0.f;
    #pragma unroll
    for (int i = 0; i < 8; i++) q += d[i] * d[i];
    const float var = block_sum256(q) * (1.0f / 2048.0f);
    const float rs = rsqrtf(var + 1e-5f);

    const float4 g0 = *(const float4*)&gw[c0];
    const float4 g1 = *(const float4*)&gw[c0 + 4];
    const float4 b0 = *(const float4*)&bw[c0];
    const float4 b1 = *(const float4*)&bw[c0 + 4];
    const float ga[8] = {g0.x, g0.y, g0.z, g0.w, g1.x, g1.y, g1.z, g1.w};
    const float ba[8] = {b0.x, b0.y, b0.z, b0.w, b1.x, b1.y, b1.z, b1.w};

    float o[8];
    #pragma unroll
    for (int i = 0; i < 8; i++) o[i] = to_tf32(d[i] * rs * ga[i] + ba[i]);

    #pragma unroll
    for (int i = 0; i < 4; i++)
        *(float2*)&y[base + c0 + (i << 1)] = make_float2(o[i], o[i + 4]);
}

// ---------------- TF32 GEMM: pointer-inc copies, 1 barrier/k-tile ----------
// C[M,N] = A[M,K] @ Wt[N,K]^T (+bias)(+res)(+gelu)(rnd). A,Wt k-permuted.
// CTA 128x128, K-tile 32, 8 warps 4(m)x2(n). 3 stages x 32KB = 96KB smem.
#define GSMEM 98304

template<int ACT, int HASRES, int RND, int PERMC>
__global__ __launch_bounds__(256, 2) void gemm_cp(
    const float* __restrict__ A, const float* __restrict__ Wt,
    const float* __restrict__ bias, const float* __restrict__ res,
    float* __restrict__ C, int M, int N, int K)
{
    extern __shared__ float sm[];
    const uint32_t sb = smem_u32(sm);
    const int tid = threadIdx.x;
    const int warp = tid >> 5, lane = tid & 31;
    const int wm = warp >> 1, wn = warp & 1;
    const int g = lane >> 2, t4 = lane & 3;
    const int bm = blockIdx.y << 7, bn = blockIdx.x << 7;

    const float* Ab = A  + (size_t)bm * K;
    const float* Bb = Wt + (size_t)bn * K;
    const int KT = K >> 5;

    // copy geometry: running global pointers + fixed swizzled smem offsets
    const int r0 = tid >> 3;
    const int cc = (tid & 7) << 2;
    const uint32_t dcol = (uint32_t)((cc ^ ((r0 & 3) << 3)) << 2);  // bytes
    const float* ga[4]; const float* gb[4];
    uint32_t da[4], db[4];
    #pragma unroll
    for (int i = 0; i < 4; i++) {
        const int row = r0 + (i << 5);
        ga[i] = Ab + (size_t)row * K + cc;
        gb[i] = Bb + (size_t)row * K + cc;
        da[i] = (uint32_t)(row * 128) + dcol;
        db[i] = 16384u + (uint32_t)(row * 128) + dcol;
    }

    float acc[2][8][4];
    #pragma unroll
    for (int a = 0; a < 2; a++)
        #pragma unroll
        for (int b2 = 0; b2 < 8; b2++)
            #pragma unroll
            for (int c = 0; c < 4; c++) acc[a][b2][c] = 0.f;

    auto issue = [&](int s) {
        const uint32_t st = sb + (uint32_t)s * 32768u;
        #pragma unroll
        for (int i = 0; i < 4; i++) { cp16(st + da[i], ga[i]); ga[i] += 32; }
        #pragma unroll
        for (int i = 0; i < 4; i++) { cp16(st + db[i], gb[i]); gb[i] += 32; }
        asm volatile("cp.async.commit_group;" ::: "memory");
    };

    issue(0);
    issue(1);

    // fragment k-offsets: ((ks<<3) ^ swz) | (t4<<1)  (disjoint bit-fields)
    const int swz = (g & 3) << 3;
    int kcs[4];
    #pragma unroll
    for (int ks = 0; ks < 4; ks++) kcs[ks] = ((ks << 3) ^ swz) | (t4 << 1);

    int s = 0;
    for (int kt = 0; kt < KT; kt++) {
        if (kt + 1 < KT) asm volatile("cp.async.wait_group 1;" ::: "memory");
        else             asm volatile("cp.async.wait_group 0;" ::: "memory");
        __syncthreads();   // single barrier: orders copies + prev-iter reads
        if (kt + 2 < KT) {
            int ns = s + 2; if (ns >= 3) ns -= 3;
            issue(ns);
        }
        const float* As = sm + s * 8192;
        const float* Bs = As + 4096;

        #pragma unroll
        for (int ks = 0; ks < 4; ks++) {
            const int kc = kcs[ks];
            uint32_t af[2][4];
            #pragma unroll
            for (int mi = 0; mi < 2; mi++) {
                const int mr = (wm << 5) + (mi << 4) + g;
                const float2 a02 = *(const float2*)&As[mr * 32 + kc];
                const float2 a13 = *(const float2*)&As[(mr + 8) * 32 + kc];
                af[mi][0] = __float_as_uint(a02.x);
                af[mi][1] = __float_as_uint(a13.x);
                af[mi][2] = __float_as_uint(a02.y);
                af[mi][3] = __float_as_uint(a13.y);
            }
            #pragma unroll
            for (int ni = 0; ni < 8; ni++) {
                const int nc = (wn << 6) + (ni << 3) + g;
                const float2 b01 = *(const float2*)&Bs[nc * 32 + kc];
                uint32_t bf[2];
                bf[0] = __float_as_uint(b01.x);
                bf[1] = __float_as_uint(b01.y);
                mma8(acc[0][ni], af[0], bf);
                mma8(acc[1][ni], af[1], bf);
            }
        }
        if (++s == 3) s = 0;
    }

    // epilogue
    #pragma unroll
    for (int mi = 0; mi < 2; mi++) {
        const int row0 = bm + (wm << 5) + (mi << 4) + g;
        #pragma unroll
        for (int ni = 0; ni < 8; ni++) {
            const int base = bn + (wn << 6) + (ni << 3);
            const int lcol = base + (t4 << 1);
            const float b0 = bias[lcol], b1 = bias[lcol + 1];
            float v00 = acc[mi][ni][0] + b0, v01 = acc[mi][ni][1] + b1;
            float v10 = acc[mi][ni][2] + b0, v11 = acc[mi][ni][3] + b1;
            const size_t i0 = (size_t)row0 * N + lcol;
            const size_t i1 = i0 + (size_t)8 * N;
            if (HASRES) {
                v00 += res[i0]; v01 += res[i0 + 1];
                v10 += res[i1]; v11 += res[i1 + 1];
            }
            if (ACT == 1) {
                v00 = to_tf32(gelu_f(v00)); v01 = to_tf32(gelu_f(v01));
                v10 = to_tf32(gelu_f(v10)); v11 = to_tf32(gelu_f(v11));
            } else if (RND) {
                v00 = to_tf32(v00); v01 = to_tf32(v01);
                v10 = to_tf32(v10); v11 = to_tf32(v11);
            }
            if (PERMC) {
                const int p0 = (t4 < 2) ? (t4 << 2) : ((t4 << 2) - 7);
                const size_t r0i = (size_t)row0 * N + base;
                const size_t r1i = r0i + (size_t)8 * N;
                C[r0i + p0] = v00; C[r0i + p0 + 2] = v01;
                C[r1i + p0] = v10; C[r1i + p0 + 2] = v11;
            } else {
                *(float2*)&C[i0] = make_float2(v00, v01);
                *(float2*)&C[i1] = make_float2(v10, v11);
            }
        }
    }
}

// ---------------- causal flash attention (tf32 mma, poly-exp softmax) ------
#define FSMEM 119552

__global__ __launch_bounds__(256) void flash_kernel(
    const float* __restrict__ QKV, float* __restrict__ O)
{
    extern __shared__ float smf[];
    float* Qs   = smf;                 // [64][132]
    float* Ks   = smf + 8448;          // [64][132]
    float* Vs   = smf + 16896;         // [64][132]
    float* Ss   = smf + 25344;         // [64][68]
    float* mrow = smf + 29696;
    float* lrow = smf + 29760;
    float* arow = smf + 29824;

    const int tid = threadIdx.x;
    const int warp = tid >> 5, lane = tid & 31;
    const int g = lane >> 2, t4 = lane & 3;
    const int wm = warp >> 1, wn = warp & 1;
    const int b = blockIdx.y >> 4, h = blockIdx.y & 15;
    const int q0 = blockIdx.x << 6;
    const size_t qbase = (size_t)b * 2048 * 6144 + (size_t)h * 128;
    const float* Qg = QKV + qbase;
    const float* Kg = QKV + qbase + 2048;
    const float* Vg = QKV + qbase + 4096;
    float*       Og = O + ((size_t)b * 2048) * 2048 + (size_t)h * 128;

    #pragma unroll
    for (int rr = 0; rr < 8; rr++) {
        const int f4 = tid + (rr << 8);
        const int row = f4 >> 5, c4 = f4 & 31;
        *(float4*)&Qs[row * 132 + (c4 << 2)] =
            *(const float4*)&Qg[(size_t)(q0 + row) * 6144 + (c4 << 2)];
    }
    if (tid < 64) { mrow[tid] = -1e30f; lrow[tid] = 0.f; }

    float o[2][4][4];
    #pragma unroll
    for (int mi = 0; mi < 2; mi++)
        #pragma unroll
        for (int ni = 0; ni < 4; ni++)
            #pragma unroll
            for (int c = 0; c < 4; c++) o[mi][ni][c] = 0.f;

    const int ntile = (q0 >> 6) + 1;
    for (int kt = 0; kt < ntile; kt++) {
        const int k0 = kt << 6;
        __syncthreads();
        #pragma unroll
        for (int rr = 0; rr < 8; rr++) {
            const int f4 = tid + (rr << 8);
            const int row = f4 >> 5, c4 = f4 & 31;
            *(float4*)&Ks[row * 132 + (c4 << 2)] =
                *(const float4*)&Kg[(size_t)(k0 + row) * 6144 + (c4 << 2)];
            *(float4*)&Vs[row * 132 + (c4 << 2)] =
                *(const float4*)&Vg[(size_t)(k0 + row) * 6144 + (c4 << 2)];
        }
        __syncthreads();

        // S = Q K^T (warp tile 16x32)
        {
            float sacc[4][4];
            #pragma unroll
            for (int ni = 0; ni < 4; ni++)
                #pragma unroll
                for (int c = 0; c < 4; c++) sacc[ni][c] = 0.f;
            const int m0 = wm << 4;
            #pragma unroll
            for (int kk = 0; kk < 16; kk++) {
                const int kb = kk << 3;
                uint32_t af[4];
                af[0] = __float_as_uint(Qs[(m0 + g    ) * 132 + kb + t4    ]);
                af[1] = __float_as_uint(Qs[(m0 + g + 8) * 132 + kb + t4    ]);
                af[2] = __float_as_uint(Qs[(m0 + g    ) * 132 + kb + t4 + 4]);
                af[3] = __float_as_uint(Qs[(m0 + g + 8) * 132 + kb + t4 + 4]);
                #pragma unroll
                for (int ni = 0; ni < 4; ni++) {
                    const int n = (wn << 5) + (ni << 3) + g;
                    uint32_t bf[2];
                    bf[0] = __float_as_uint(Ks[n * 132 + kb + t4    ]);
                    bf[1] = __float_as_uint(Ks[n * 132 + kb + t4 + 4]);
                    mma8(sacc[ni], af, bf);
                }
            }
            #pragma unroll
            for (int ni = 0; ni < 4; ni++) {
                const int col = (wn << 5) + (ni << 3) + (t4 << 1);
                const int r0 = m0 + g, r1 = m0 + g + 8;
                float v00 = sacc[ni][0] * 0.08838834764831845f;
                float v01 = sacc[ni][1] * 0.08838834764831845f;
                float v10 = sacc[ni][2] * 0.08838834764831845f;
                float v11 = sacc[ni][3] * 0.08838834764831845f;
                if (k0 + col     > q0 + r0) v00 = -1e30f;
                if (k0 + col + 1 > q0 + r0) v01 = -1e30f;
                if (k0 + col     > q0 + r1) v10 = -1e30f;
                if (k0 + col + 1 > q0 + r1) v11 = -1e30f;
                Ss[r0 * 68 + col] = v00; Ss[r0 * 68 + col + 1] = v01;
                Ss[r1 * 68 + col] = v10; Ss[r1 * 68 + col + 1] = v11;
            }
        }
        __syncthreads();

        // online softmax; P tf32-rounded; exp via FMA-pipe poly (no MUFU)
        {
            const int rid = tid >> 2, c0 = tid & 3;
            float mx = -1e30f;
            #pragma unroll
            for (int jc = c0; jc < 64; jc += 4) mx = fmaxf(mx, Ss[rid * 68 + jc]);
            mx = fmaxf(mx, __shfl_xor_sync(0xffffffffu, mx, 1));
            mx = fmaxf(mx, __shfl_xor_sync(0xffffffffu, mx, 2));
            const float mold = mrow[rid];
            const float mnew = fmaxf(mold, mx);
            float sum = 0.f;
            #pragma unroll
            for (int jc = c0; jc < 64; jc += 4) {
                const float p = to_tf32(fexp(Ss[rid * 68 + jc] - mnew));
                Ss[rid * 68 + jc] = p;
                sum += p;
            }
            sum += __shfl_xor_sync(0xffffffffu, sum, 1);
            sum += __shfl_xor_sync(0xffffffffu, sum, 2);
            if (c0 == 0) {
                arow[rid] = fexp(mold - mnew);
                lrow[rid] = lrow[rid] * arow[rid] + sum;
                mrow[rid] = mnew;
            }
        }
        __syncthreads();

        // O^T += V^T @ P^T (warp tile 32d x 32q)
        {
            const int d0 = wm << 5, qw = wn << 5;
            #pragma unroll
            for (int ni = 0; ni < 4; ni++) {
                const int cq = qw + (ni << 3) + (t4 << 1);
                const float a0 = arow[cq], a1 = arow[cq + 1];
                #pragma unroll
                for (int mi = 0; mi < 2; mi++) {
                    o[mi][ni][0] *= a0; o[mi][ni][1] *= a1;
                    o[mi][ni][2] *= a0; o[mi][ni][3] *= a1;
                }
            }
            #pragma unroll
            for (int k_ = 0; k_ < 8; k_++) {
                const int kb = k_ << 3;
                uint32_t af[2][4];
                #pragma unroll
                for (int mi = 0; mi < 2; mi++) {
                    const int dm = d0 + (mi << 4);
                    af[mi][0] = __float_as_uint(Vs[(kb + t4    ) * 132 + dm + g    ]);
                    af[mi][1] = __float_as_uint(Vs[(kb + t4    ) * 132 + dm + g + 8]);
                    af[mi][2] = __float_as_uint(Vs[(kb + t4 + 4) * 132 + dm + g    ]);
                    af[mi][3] = __float_as_uint(Vs[(kb + t4 + 4) * 132 + dm + g + 8]);
                }
                #pragma unroll
                for (int ni = 0; ni < 4; ni++) {
                    const int nq = qw + (ni << 3) + g;
                    uint32_t bf[2];
                    bf[0] = __float_as_uint(Ss[nq * 68 + kb + t4    ]);
                    bf[1] = __float_as_uint(Ss[nq * 68 + kb + t4 + 4]);
                    mma8(o[0][ni], af[0], bf);
                    mma8(o[1][ni], af[1], bf);
                }
            }
        }
    }

    // normalize + store O[q][d], d-index k-permuted for next GEMM's A
    __syncthreads();
    {
        const int d0 = wm << 5, qw = wn << 5;
        const int pg = (g < 4) ? (g << 1) : ((g << 1) - 7);
        #pragma unroll
        for (int ni = 0; ni < 4; ni++) {
            const int cq = qw + (ni << 3) + (t4 << 1);
            const float inv0 = 1.0f / lrow[cq], inv1 = 1.0f / lrow[cq + 1];
            #pragma unroll
            for (int mi = 0; mi < 2; mi++) {
                const int db = d0 + (mi << 4);
                Og[(size_t)(q0 + cq    ) * 2048 + db + pg    ] = to_tf32(o[mi][ni][0] * inv0);
                Og[(size_t)(q0 + cq + 1) * 2048 + db + pg    ] = to_tf32(o[mi][ni][1] * inv1);
                Og[(size_t)(q0 + cq    ) * 2048 + db + 8 + pg] = to_tf32(o[mi][ni][2] * inv0);
                Og[(size_t)(q0 + cq + 1) * 2048 + db + 8 + pg] = to_tf32(o[mi][ni][3] * inv1);
            }
        }
    }
}

// ---------------- host orchestration ---------------------------------------
extern "C" void kernel_launch(void* const* d_in, const int* in_sizes, int n_in,
                              void* d_out, int out_size)
{
    const float* x     = (const float*)d_in[0];
    const float* ln1_g = (const float*)d_in[2];
    const float* ln1_b = (const float*)d_in[3];
    const float* wq    = (const float*)d_in[4];
    const float* bq    = (const float*)d_in[5];
    const float* wk    = (const float*)d_in[6];
    const float* bk    = (const float*)d_in[7];
    const float* wv    = (const float*)d_in[8];
    const float* bv    = (const float*)d_in[9];
    const float* wo    = (const float*)d_in[10];
    const float* bo    = (const float*)d_in[11];
    const float* ln2_g = (const float*)d_in[12];
    const float* ln2_b = (const float*)d_in[13];
    const float* w_in  = (const float*)d_in[14];
    const float* b_in  = (const float*)d_in[15];
    const float* w_out = (const float*)d_in[16];
    const float* b_out = (const float*)d_in[17];
    float* out = (float*)d_out;

    float *xn, *qkv, *attn, *x1, *h, *wqkvt, *wot, *wint, *woutt, *bqkv;
    cudaGetSymbolAddress((void**)&xn,     g_xn);
    cudaGetSymbolAddress((void**)&qkv,    g_qkv);
    cudaGetSymbolAddress((void**)&attn,   g_attn);
    cudaGetSymbolAddress((void**)&x1,     g_x1);
    cudaGetSymbolAddress((void**)&h,      g_h);
    cudaGetSymbolAddress((void**)&wqkvt,  g_wqkvt);
    cudaGetSymbolAddress((void**)&wot,    g_wot);
    cudaGetSymbolAddress((void**)&wint,   g_wint);
    cudaGetSymbolAddress((void**)&woutt,  g_woutt);
    cudaGetSymbolAddress((void**)&bqkv,   g_bqkv);

    cudaFuncSetAttribute(flash_kernel,
                         cudaFuncAttributeMaxDynamicSharedMemorySize, FSMEM);
    cudaFuncSetAttribute(gemm_cp<0,0,1,0>,
                         cudaFuncAttributeMaxDynamicSharedMemorySize, GSMEM);
    cudaFuncSetAttribute(gemm_cp<0,1,0,0>,
                         cudaFuncAttributeMaxDynamicSharedMemorySize, GSMEM);
    cudaFuncSetAttribute(gemm_cp<1,0,0,1>,
                         cudaFuncAttributeMaxDynamicSharedMemorySize, GSMEM);

    prep_a<<<12312, 256>>>(wq, wk, wv, bq, bk, bv);                     // 1
    prep_b<<<36864, 256>>>(wo, w_in, w_out);                            // 2
    ln_kernel<<<4096, 256>>>(x, ln1_g, ln1_b, xn);                      // 3
    gemm_cp<0,0,1,0><<<dim3(48, 32), 256, GSMEM>>>(                     // 4: QKV
        xn, wqkvt, bqkv, nullptr, qkv, 4096, 6144, 2048);
    flash_kernel<<<dim3(32, 32), 256, FSMEM>>>(qkv, attn);              // 5
    gemm_cp<0,1,0,0><<<dim3(16, 32), 256, GSMEM>>>(                     // 6: O-proj
        attn, wot, bo, x, x1, 4096, 2048, 2048);
    ln_kernel<<<4096, 256>>>(x1, ln2_g, ln2_b, xn);                     // 7
    gemm_cp<1,0,0,1><<<dim3(64, 32), 256, GSMEM>>>(                     // 8: MLP in
        xn, wint, b_in, nullptr, h, 4096, 8192, 2048);
    gemm_cp<0,1,0,0><<<dim3(16, 32), 256, GSMEM>>>(                     // 9: MLP out
        h, woutt, b_out, x1, out, 4096, 2048, 8192);
}

// round 12
// speedup vs baseline: 1.1599x; 1.0004x over previous
#include <cuda_runtime.h>
#include <cstdint>
#include <math.h>

// Problem dims: B=2, S=2048, D=2048, H=16, DH=128, DFF=8192
#define BSD 8388608   // B*S*D
#define BSF 33554432  // B*S*DFF

// ---------------- scratch (static device globals; no runtime allocation) ---
__device__ float g_xn[BSD];         // LN out (k-permuted along D)
__device__ float g_qkv[25165824];   // [4096][6144] q|k|v
__device__ float g_attn[BSD];       // flash out (k-permuted along D)
__device__ float g_x1[BSD];
__device__ float g_h[BSF];          // gelu out (k-permuted along DFF)
// transposed [N,K] + tf32-rounded + k-permuted weights
__device__ float g_wqkvt[12582912]; // [6144][2048]
__device__ float g_wot[4194304];    // [2048][2048]
__device__ float g_wint[16777216];  // [8192][2048]
__device__ float g_woutt[16777216]; // [2048][8192]
__device__ float g_bqkv[6144];

// ---------------- helpers --------------------------------------------------
__device__ __forceinline__ float to_tf32(float x) {
    float r; asm("cvt.rna.tf32.f32 %0, %1;" : "=f"(r) : "f"(x)); return r;
}
__device__ __forceinline__ uint32_t smem_u32(const void* p) {
    uint32_t a;
    asm("{ .reg .u64 t; cvta.to.shared.u64 t, %1; cvt.u32.u64 %0, t; }"
        : "=r"(a) : "l"(p));
    return a;
}
__device__ __forceinline__ void cp16(uint32_t s, const void* g) {
    asm volatile("cp.async.cg.shared.global [%0], [%1], 16;" :: "r"(s), "l"(g));
}
__device__ __forceinline__ void mma8(float* d, const uint32_t* a, const uint32_t* b) {
    asm volatile(
        "mma.sync.aligned.m16n8k8.row.col.f32.tf32.tf32.f32 "
        "{%0,%1,%2,%3}, {%4,%5,%6,%7}, {%8,%9}, {%0,%1,%2,%3};\n"
        : "+f"(d[0]), "+f"(d[1]), "+f"(d[2]), "+f"(d[3])
        : "r"(a[0]), "r"(a[1]), "r"(a[2]), "r"(a[3]), "r"(b[0]), "r"(b[1]));
}
__device__ __forceinline__ float gelu_f(float v) {
    return 0.5f * v * (1.0f + erff(v * 0.70710678118654752f));
}
// fast exp via FMA-pipe poly (avoids MUFU bottleneck). x <= ~0 expected;
// very negative x (mask -1e30) clamps to ~0. rel err ~2e-6.
__device__ __forceinline__ float fexp(float x) {
    float y = x * 1.4426950408889634f;          // log2(e)
    y = fmaxf(y, -126.0f);
    const float magic = 12582912.0f;            // 1.5 * 2^23
    const float z = y + magic;
    const int   n = __float_as_int(z) - 0x4B400000;
    const float f = y - (z - magic);            // f in [-0.5, 0.5]
    float r = 0.0013333558f;
    r = fmaf(r, f, 0.0096181291f);
    r = fmaf(r, f, 0.0555041087f);
    r = fmaf(r, f, 0.2402265069f);
    r = fmaf(r, f, 0.6931471806f);
    r = fmaf(r, f, 1.0f);
    return __int_as_float(__float_as_int(r) + (n << 23));
}
// k-permutation within 8-groups: logical l -> phys (l<4 ? 2l : 2(l-4)+1)
__device__ __forceinline__ int permc(int x) {
    const int l = x & 7;
    return (x & 24) | ((l < 4) ? (l << 1) : (((l - 4) << 1) | 1));
}

// ---------------- weight prep: transpose [K,N]->[N,K], round, k-permute ----
__device__ void tp_tile(const float* __restrict__ src, float* __restrict__ dst,
                        int K, int N, int t)
{
    __shared__ float tbuf[32][33];
    const int tn = N >> 5;
    const int n0 = (t % tn) << 5, k0 = (t / tn) << 5;
    const int x = threadIdx.x & 31, y = threadIdx.x >> 5;
    #pragma unroll
    for (int i = 0; i < 32; i += 8)
        tbuf[y + i][x] = src[(size_t)(k0 + y + i) * N + n0 + x];
    __syncthreads();
    const int kp = k0 + permc(x);
    #pragma unroll
    for (int i = 0; i < 32; i += 8)
        dst[(size_t)(n0 + y + i) * K + kp] = to_tf32(tbuf[x][y + i]);
}

__global__ __launch_bounds__(256) void prep_a(
    const float* __restrict__ wq, const float* __restrict__ wk,
    const float* __restrict__ wv, const float* __restrict__ bq,
    const float* __restrict__ bk, const float* __restrict__ bv)
{
    const int blk = blockIdx.x;
    if (blk < 12288) {
        const int w = blk >> 12, t = blk & 4095;
        const float* src = (w == 0) ? wq : (w == 1) ? wk : wv;
        tp_tile(src, g_wqkvt + (size_t)w * 4194304, 2048, 2048, t);
    } else {
        const int idx = ((blk - 12288) << 8) + threadIdx.x;
        if (idx < 6144) {
            const int sel = idx >> 11;
            const float* b = (sel == 0) ? bq : (sel == 1) ? bk : bv;
            g_bqkv[idx] = b[idx & 2047];
        }
    }
}

__global__ __launch_bounds__(256) void prep_b(
    const float* __restrict__ wo, const float* __restrict__ w_in,
    const float* __restrict__ w_out)
{
    const int blk = blockIdx.x;
    if (blk < 4096)        tp_tile(wo,    g_wot,   2048, 2048, blk);
    else if (blk < 20480)  tp_tile(w_in,  g_wint,  2048, 8192, blk - 4096);
    else                   tp_tile(w_out, g_woutt, 8192, 2048, blk - 20480);
}

// ---------------- block reduce ---------------------------------------------
__device__ __forceinline__ float block_sum256(float v) {
    __shared__ float red[8];
    #pragma unroll
    for (int o = 16; o; o >>= 1) v += __shfl_xor_sync(0xffffffffu, v, o);
    const int w = threadIdx.x >> 5, l = threadIdx.x & 31;
    __syncthreads();
    if (l == 0) red[w] = v;
    __syncthreads();
    float t = red[l & 7];
    t += __shfl_xor_sync(0xffffffffu, t, 1);
    t += __shfl_xor_sync(0xffffffffu, t, 2);
    t += __shfl_xor_sync(0xffffffffu, t, 4);
    return t;
}

// ---------------- LayerNorm (tf32-rounded, k-permuted output) --------------
__global__ __launch_bounds__(256) void ln_kernel(
    const float* __restrict__ x, const float* __restrict__ gw,
    const float* __restrict__ bw, float* __restrict__ y)
{
    const size_t base = (size_t)blockIdx.x * 2048;
    const int c0 = threadIdx.x << 3;
    const float4 v0 = *(const float4*)&x[base + c0];
    const float4 v1 = *(const float4*)&x[base + c0 + 4];

    float s = v0.x + v0.y + v0.z + v0.w + v1.x + v1.y + v1.z + v1.w;
    const float mean = block_sum256(s) * (1.0f / 2048.0f);

    float d[8];
    d[0] = v0.x - mean; d[1] = v0.y - mean; d[2] = v0.z - mean; d[3] = v0.w - mean;
    d[4] = v1.x - mean; d[5] = v1.y - mean; d[6] = v1.z - mean; d[7] = v1.w - mean;
    float q = 0.f;
    #pragma unroll
    for (int i = 0; i < 8; i++) q += d[i] * d[i];
    const float var = block_sum256(q) * (1.0f / 2048.0f);
    const float rs = rsqrtf(var + 1e-5f);

    const float4 g0 = *(const float4*)&gw[c0];
    const float4 g1 = *(const float4*)&gw[c0 + 4];
    const float4 b0 = *(const float4*)&bw[c0];
    const float4 b1 = *(const float4*)&bw[c0 + 4];
    const float ga[8] = {g0.x, g0.y, g0.z, g0.w, g1.x, g1.y, g1.z, g1.w};
    const float ba[8] = {b0.x, b0.y, b0.z, b0.w, b1.x, b1.y, b1.z, b1.w};

    float o[8];
    #pragma unroll
    for (int i = 0; i < 8; i++) o[i] = to_tf32(d[i] * rs * ga[i] + ba[i]);

    #pragma unroll
    for (int i = 0; i < 4; i++)
        *(float2*)&y[base + c0 + (i << 1)] = make_float2(o[i], o[i + 4]);
}

// ---------------- TF32 GEMM: pointer-inc copies, 1 barrier/k-tile ----------
// C[M,N] = A[M,K] @ Wt[N,K]^T (+bias)(+res)(+gelu)(rnd). A,Wt k-permuted.
// CTA 128x128, K-tile 32, 8 warps 4(m)x2(n). 3 stages x 32KB = 96KB smem.
#define GSMEM 98304

template<int ACT, int HASRES, int RND, int PERMC>
__global__ __launch_bounds__(256, 2) void gemm_cp(
    const float* __restrict__ A, const float* __restrict__ Wt,
    const float* __restrict__ bias, const float* __restrict__ res,
    float* __restrict__ C, int M, int N, int K)
{
    extern __shared__ float sm[];
    const uint32_t sb = smem_u32(sm);
    const int tid = threadIdx.x;
    const int warp = tid >> 5, lane = tid & 31;
    const int wm = warp >> 1, wn = warp & 1;
    const int g = lane >> 2, t4 = lane & 3;
    const int bm = blockIdx.y << 7, bn = blockIdx.x << 7;

    const float* Ab = A  + (size_t)bm * K;
    const float* Bb = Wt + (size_t)bn * K;
    const int KT = K >> 5;

    // copy geometry: running global pointers + fixed swizzled smem offsets
    const int r0 = tid >> 3;
    const int cc = (tid & 7) << 2;
    const uint32_t dcol = (uint32_t)((cc ^ ((r0 & 3) << 3)) << 2);  // bytes
    const float* ga[4]; const float* gb[4];
    uint32_t da[4], db[4];
    #pragma unroll
    for (int i = 0; i < 4; i++) {
        const int row = r0 + (i << 5);
        ga[i] = Ab + (size_t)row * K + cc;
        gb[i] = Bb + (size_t)row * K + cc;
        da[i] = (uint32_t)(row * 128) + dcol;
        db[i] = 16384u + (uint32_t)(row * 128) + dcol;
    }

    float acc[2][8][4];
    #pragma unroll
    for (int a = 0; a < 2; a++)
        #pragma unroll
        for (int b2 = 0; b2 < 8; b2++)
            #pragma unroll
            for (int c = 0; c < 4; c++) acc[a][b2][c] = 0.f;

    auto issue = [&](int s) {
        const uint32_t st = sb + (uint32_t)s * 32768u;
        #pragma unroll
        for (int i = 0; i < 4; i++) { cp16(st + da[i], ga[i]); ga[i] += 32; }
        #pragma unroll
        for (int i = 0; i < 4; i++) { cp16(st + db[i], gb[i]); gb[i] += 32; }
        asm volatile("cp.async.commit_group;" ::: "memory");
    };

    issue(0);
    issue(1);

    // fragment k-offsets: ((ks<<3) ^ swz) | (t4<<1)  (disjoint bit-fields)
    const int swz = (g & 3) << 3;
    int kcs[4];
    #pragma unroll
    for (int ks = 0; ks < 4; ks++) kcs[ks] = ((ks << 3) ^ swz) | (t4 << 1);

    int s = 0;
    for (int kt = 0; kt < KT; kt++) {
        if (kt + 1 < KT) asm volatile("cp.async.wait_group 1;" ::: "memory");
        else             asm volatile("cp.async.wait_group 0;" ::: "memory");
        __syncthreads();   // single barrier: orders copies + prev-iter reads
        if (kt + 2 < KT) {
            int ns = s + 2; if (ns >= 3) ns -= 3;
            issue(ns);
        }
        const float* As = sm + s * 8192;
        const float* Bs = As + 4096;

        #pragma unroll
        for (int ks = 0; ks < 4; ks++) {
            const int kc = kcs[ks];
            uint32_t af[2][4];
            #pragma unroll
            for (int mi = 0; mi < 2; mi++) {
                const int mr = (wm << 5) + (mi << 4) + g;
                const float2 a02 = *(const float2*)&As[mr * 32 + kc];
                const float2 a13 = *(const float2*)&As[(mr + 8) * 32 + kc];
                af[mi][0] = __float_as_uint(a02.x);
                af[mi][1] = __float_as_uint(a13.x);
                af[mi][2] = __float_as_uint(a02.y);
                af[mi][3] = __float_as_uint(a13.y);
            }
            #pragma unroll
            for (int ni = 0; ni < 8; ni++) {
                const int nc = (wn << 6) + (ni << 3) + g;
                const float2 b01 = *(const float2*)&Bs[nc * 32 + kc];
                uint32_t bf[2];
                bf[0] = __float_as_uint(b01.x);
                bf[1] = __float_as_uint(b01.y);
                mma8(acc[0][ni], af[0], bf);
                mma8(acc[1][ni], af[1], bf);
            }
        }
        if (++s == 3) s = 0;
    }

    // epilogue
    #pragma unroll
    for (int mi = 0; mi < 2; mi++) {
        const int row0 = bm + (wm << 5) + (mi << 4) + g;
        #pragma unroll
        for (int ni = 0; ni < 8; ni++) {
            const int base = bn + (wn << 6) + (ni << 3);
            const int lcol = base + (t4 << 1);
            const float b0 = bias[lcol], b1 = bias[lcol + 1];
            float v00 = acc[mi][ni][0] + b0, v01 = acc[mi][ni][1] + b1;
            float v10 = acc[mi][ni][2] + b0, v11 = acc[mi][ni][3] + b1;
            const size_t i0 = (size_t)row0 * N + lcol;
            const size_t i1 = i0 + (size_t)8 * N;
            if (HASRES) {
                v00 += res[i0]; v01 += res[i0 + 1];
                v10 += res[i1]; v11 += res[i1 + 1];
            }
            if (ACT == 1) {
                v00 = to_tf32(gelu_f(v00)); v01 = to_tf32(gelu_f(v01));
                v10 = to_tf32(gelu_f(v10)); v11 = to_tf32(gelu_f(v11));
            } else if (RND) {
                v00 = to_tf32(v00); v01 = to_tf32(v01);
                v10 = to_tf32(v10); v11 = to_tf32(v11);
            }
            if (PERMC) {
                const int p0 = (t4 < 2) ? (t4 << 2) : ((t4 << 2) - 7);
                const size_t r0i = (size_t)row0 * N + base;
                const size_t r1i = r0i + (size_t)8 * N;
                C[r0i + p0] = v00; C[r0i + p0 + 2] = v01;
                C[r1i + p0] = v10; C[r1i + p0 + 2] = v11;
            } else {
                *(float2*)&C[i0] = make_float2(v00, v01);
                *(float2*)&C[i1] = make_float2(v10, v11);
            }
        }
    }
}

// ---------------- causal flash attention (tf32 mma, poly-exp softmax) ------
#define FSMEM 119552

__global__ __launch_bounds__(256) void flash_kernel(
    const float* __restrict__ QKV, float* __restrict__ O)
{
    extern __shared__ float smf[];
    float* Qs   = smf;                 // [64][132]
    float* Ks   = smf + 8448;          // [64][132]
    float* Vs   = smf + 16896;         // [64][132]
    float* Ss   = smf + 25344;         // [64][68]
    float* mrow = smf + 29696;
    float* lrow = smf + 29760;
    float* arow = smf + 29824;

    const int tid = threadIdx.x;
    const int warp = tid >> 5, lane = tid & 31;
    const int g = lane >> 2, t4 = lane & 3;
    const int wm = warp >> 1, wn = warp & 1;
    const int b = blockIdx.y >> 4, h = blockIdx.y & 15;
    const int q0 = blockIdx.x << 6;
    const size_t qbase = (size_t)b * 2048 * 6144 + (size_t)h * 128;
    const float* Qg = QKV + qbase;
    const float* Kg = QKV + qbase + 2048;
    const float* Vg = QKV + qbase + 4096;
    float*       Og = O + ((size_t)b * 2048) * 2048 + (size_t)h * 128;

    #pragma unroll
    for (int rr = 0; rr < 8; rr++) {
        const int f4 = tid + (rr << 8);
        const int row = f4 >> 5, c4 = f4 & 31;
        *(float4*)&Qs[row * 132 + (c4 << 2)] =
            *(const float4*)&Qg[(size_t)(q0 + row) * 6144 + (c4 << 2)];
    }
    if (tid < 64) { mrow[tid] = -1e30f; lrow[tid] = 0.f; }

    float o[2][4][4];
    #pragma unroll
    for (int mi = 0; mi < 2; mi++)
        #pragma unroll
        for (int ni = 0; ni < 4; ni++)
            #pragma unroll
            for (int c = 0; c < 4; c++) o[mi][ni][c] = 0.f;

    const int ntile = (q0 >> 6) + 1;
    for (int kt = 0; kt < ntile; kt++) {
        const int k0 = kt << 6;
        __syncthreads();
        #pragma unroll
        for (int rr = 0; rr < 8; rr++) {
            const int f4 = tid + (rr << 8);
            const int row = f4 >> 5, c4 = f4 & 31;
            *(float4*)&Ks[row * 132 + (c4 << 2)] =
                *(const float4*)&Kg[(size_t)(k0 + row) * 6144 + (c4 << 2)];
            *(float4*)&Vs[row * 132 + (c4 << 2)] =
                *(const float4*)&Vg[(size_t)(k0 + row) * 6144 + (c4 << 2)];
        }
        __syncthreads();

        // S = Q K^T (warp tile 16x32)
        {
            float sacc[4][4];
            #pragma unroll
            for (int ni = 0; ni < 4; ni++)
                #pragma unroll
                for (int c = 0; c < 4; c++) sacc[ni][c] = 0.f;
            const int m0 = wm << 4;
            #pragma unroll
            for (int kk = 0; kk < 16; kk++) {
                const int kb = kk << 3;
                uint32_t af[4];
                af[0] = __float_as_uint(Qs[(m0 + g    ) * 132 + kb + t4    ]);
                af[1] = __float_as_uint(Qs[(m0 + g + 8) * 132 + kb + t4    ]);
                af[2] = __float_as_uint(Qs[(m0 + g    ) * 132 + kb + t4 + 4]);
                af[3] = __float_as_uint(Qs[(m0 + g + 8) * 132 + kb + t4 + 4]);
                #pragma unroll
                for (int ni = 0; ni < 4; ni++) {
                    const int n = (wn << 5) + (ni << 3) + g;
                    uint32_t bf[2];
                    bf[0] = __float_as_uint(Ks[n * 132 + kb + t4    ]);
                    bf[1] = __float_as_uint(Ks[n * 132 + kb + t4 + 4]);
                    mma8(sacc[ni], af, bf);
                }
            }
            #pragma unroll
            for (int ni = 0; ni < 4; ni++) {
                const int col = (wn << 5) + (ni << 3) + (t4 << 1);
                const int r0 = m0 + g, r1 = m0 + g + 8;
                float v00 = sacc[ni][0] * 0.08838834764831845f;
                float v01 = sacc[ni][1] * 0.08838834764831845f;
                float v10 = sacc[ni][2] * 0.08838834764831845f;
                float v11 = sacc[ni][3] * 0.08838834764831845f;
                if (k0 + col     > q0 + r0) v00 = -1e30f;
                if (k0 + col + 1 > q0 + r0) v01 = -1e30f;
                if (k0 + col     > q0 + r1) v10 = -1e30f;
                if (k0 + col + 1 > q0 + r1) v11 = -1e30f;
                Ss[r0 * 68 + col] = v00; Ss[r0 * 68 + col + 1] = v01;
                Ss[r1 * 68 + col] = v10; Ss[r1 * 68 + col + 1] = v11;
            }
        }
        __syncthreads();

        // online softmax; P tf32-rounded; exp via FMA-pipe poly (no MUFU)
        {
            const int rid = tid >> 2, c0 = tid & 3;
            float mx = -1e30f;
            #pragma unroll
            for (int jc = c0; jc < 64; jc += 4) mx = fmaxf(mx, Ss[rid * 68 + jc]);
            mx = fmaxf(mx, __shfl_xor_sync(0xffffffffu, mx, 1));
            mx = fmaxf(mx, __shfl_xor_sync(0xffffffffu, mx, 2));
            const float mold = mrow[rid];
            const float mnew = fmaxf(mold, mx);
            float sum = 0.f;
            #pragma unroll
            for (int jc = c0; jc < 64; jc += 4) {
                const float p = to_tf32(fexp(Ss[rid * 68 + jc] - mnew));
                Ss[rid * 68 + jc] = p;
                sum += p;
            }
            sum += __shfl_xor_sync(0xffffffffu, sum, 1);
            sum += __shfl_xor_sync(0xffffffffu, sum, 2);
            if (c0 == 0) {
                arow[rid] = fexp(mold - mnew);
                lrow[rid] = lrow[rid] * arow[rid] + sum;
                mrow[rid] = mnew;
            }
        }
        __syncthreads();

        // O^T += V^T @ P^T (warp tile 32d x 32q)
        {
            const int d0 = wm << 5, qw = wn << 5;
            #pragma unroll
            for (int ni = 0; ni < 4; ni++) {
                const int cq = qw + (ni << 3) + (t4 << 1);
                const float a0 = arow[cq], a1 = arow[cq + 1];
                #pragma unroll
                for (int mi = 0; mi < 2; mi++) {
                    o[mi][ni][0] *= a0; o[mi][ni][1] *= a1;
                    o[mi][ni][2] *= a0; o[mi][ni][3] *= a1;
                }
            }
            #pragma unroll
            for (int k_ = 0; k_ < 8; k_++) {
                const int kb = k_ << 3;
                uint32_t af[2][4];
                #pragma unroll
                for (int mi = 0; mi < 2; mi++) {
                    const int dm = d0 + (mi << 4);
                    af[mi][0] = __float_as_uint(Vs[(kb + t4    ) * 132 + dm + g    ]);
                    af[mi][1] = __float_as_uint(Vs[(kb + t4    ) * 132 + dm + g + 8]);
                    af[mi][2] = __float_as_uint(Vs[(kb + t4 + 4) * 132 + dm + g    ]);
                    af[mi][3] = __float_as_uint(Vs[(kb + t4 + 4) * 132 + dm + g + 8]);
                }
                #pragma unroll
                for (int ni = 0; ni < 4; ni++) {
                    const int nq = qw + (ni << 3) + g;
                    uint32_t bf[2];
                    bf[0] = __float_as_uint(Ss[nq * 68 + kb + t4    ]);
                    bf[1] = __float_as_uint(Ss[nq * 68 + kb + t4 + 4]);
                    mma8(o[0][ni], af[0], bf);
                    mma8(o[1][ni], af[1], bf);
                }
            }
        }
    }

    // normalize + store O[q][d], d-index k-permuted for next GEMM's A
    __syncthreads();
    {
        const int d0 = wm << 5, qw = wn << 5;
        const int pg = (g < 4) ? (g << 1) : ((g << 1) - 7);
        #pragma unroll
        for (int ni = 0; ni < 4; ni++) {
            const int cq = qw + (ni << 3) + (t4 << 1);
            const float inv0 = 1.0f / lrow[cq], inv1 = 1.0f / lrow[cq + 1];
            #pragma unroll
            for (int mi = 0; mi < 2; mi++) {
                const int db = d0 + (mi << 4);
                Og[(size_t)(q0 + cq    ) * 2048 + db + pg    ] = to_tf32(o[mi][ni][0] * inv0);
                Og[(size_t)(q0 + cq + 1) * 2048 + db + pg    ] = to_tf32(o[mi][ni][1] * inv1);
                Og[(size_t)(q0 + cq    ) * 2048 + db + 8 + pg] = to_tf32(o[mi][ni][2] * inv0);
                Og[(size_t)(q0 + cq + 1) * 2048 + db + 8 + pg] = to_tf32(o[mi][ni][3] * inv1);
            }
        }
    }
}

// ---------------- host orchestration ---------------------------------------
extern "C" void kernel_launch(void* const* d_in, const int* in_sizes, int n_in,
                              void* d_out, int out_size)
{
    const float* x     = (const float*)d_in[0];
    const float* ln1_g = (const float*)d_in[2];
    const float* ln1_b = (const float*)d_in[3];
    const float* wq    = (const float*)d_in[4];
    const float* bq    = (const float*)d_in[5];
    const float* wk    = (const float*)d_in[6];
    const float* bk    = (const float*)d_in[7];
    const float* wv    = (const float*)d_in[8];
    const float* bv    = (const float*)d_in[9];
    const float* wo    = (const float*)d_in[10];
    const float* bo    = (const float*)d_in[11];
    const float* ln2_g = (const float*)d_in[12];
    const float* ln2_b = (const float*)d_in[13];
    const float* w_in  = (const float*)d_in[14];
    const float* b_in  = (const float*)d_in[15];
    const float* w_out = (const float*)d_in[16];
    const float* b_out = (const float*)d_in[17];
    float* out = (float*)d_out;

    float *xn, *qkv, *attn, *x1, *h, *wqkvt, *wot, *wint, *woutt, *bqkv;
    cudaGetSymbolAddress((void**)&xn,     g_xn);
    cudaGetSymbolAddress((void**)&qkv,    g_qkv);
    cudaGetSymbolAddress((void**)&attn,   g_attn);
    cudaGetSymbolAddress((void**)&x1,     g_x1);
    cudaGetSymbolAddress((void**)&h,      g_h);
    cudaGetSymbolAddress((void**)&wqkvt,  g_wqkvt);
    cudaGetSymbolAddress((void**)&wot,    g_wot);
    cudaGetSymbolAddress((void**)&wint,   g_wint);
    cudaGetSymbolAddress((void**)&woutt,  g_woutt);
    cudaGetSymbolAddress((void**)&bqkv,   g_bqkv);

    cudaFuncSetAttribute(flash_kernel,
                         cudaFuncAttributeMaxDynamicSharedMemorySize, FSMEM);
    cudaFuncSetAttribute(gemm_cp<0,0,1,0>,
                         cudaFuncAttributeMaxDynamicSharedMemorySize, GSMEM);
    cudaFuncSetAttribute(gemm_cp<0,1,0,0>,
                         cudaFuncAttributeMaxDynamicSharedMemorySize, GSMEM);
    cudaFuncSetAttribute(gemm_cp<1,0,0,1>,
                         cudaFuncAttributeMaxDynamicSharedMemorySize, GSMEM);

    prep_a<<<12312, 256>>>(wq, wk, wv, bq, bk, bv);                     // 1
    prep_b<<<36864, 256>>>(wo, w_in, w_out);                            // 2
    ln_kernel<<<4096, 256>>>(x, ln1_g, ln1_b, xn);                      // 3
    gemm_cp<0,0,1,0><<<dim3(48, 32), 256, GSMEM>>>(                     // 4: QKV
        xn, wqkvt, bqkv, nullptr, qkv, 4096, 6144, 2048);
    flash_kernel<<<dim3(32, 32), 256, FSMEM>>>(qkv, attn);              // 5
    gemm_cp<0,1,0,0><<<dim3(16, 32), 256, GSMEM>>>(                     // 6: O-proj
        attn, wot, bo, x, x1, 4096, 2048, 2048);
    ln_kernel<<<4096, 256>>>(x1, ln2_g, ln2_b, xn);                     // 7
    gemm_cp<1,0,0,1><<<dim3(64, 32), 256, GSMEM>>>(                     // 8: MLP in
        xn, wint, b_in, nullptr, h, 4096, 8192, 2048);
    gemm_cp<0,1,0,0><<<dim3(16, 32), 256, GSMEM>>>(                     // 9: MLP out
        h, woutt, b_out, x1, out, 4096, 2048, 8192);
}

// round 14
// speedup vs baseline: 1.1834x; 1.0203x over previous
#include <cuda_runtime.h>
#include <cstdint>
#include <math.h>

#define BSD 8388608
#define BSF 33554432

__device__ float g_xn[BSD];
__device__ float g_qkv[25165824];
__device__ float g_attn[BSD];
__device__ float g_x1[BSD];
__device__ float g_h[BSF];
__device__ float g_wqkvt[12582912];
__device__ float g_wot[4194304];
__device__ float g_wint[16777216];
__device__ float g_woutt[16777216];
__device__ float g_bqkv[6144];

__device__ __forceinline__ float to_tf32(float x) {
    float r; asm("cvt.rna.tf32.f32 %0, %1;" : "=f"(r) : "f"(x)); return r;
}
__device__ __forceinline__ uint32_t smem_u32(const void* p) {
    uint32_t a;
    asm("{ .reg .u64 t; cvta.to.shared.u64 t, %1; cvt.u32.u64 %0, t; }"
        : "=r"(a) : "l"(p));
    return a;
}
__device__ __forceinline__ void cp16(uint32_t s, const void* g) {
    asm volatile("cp.async.cg.shared.global [%0], [%1], 16;" :: "r"(s), "l"(g));
}
__device__ __forceinline__ void mma8(float* d, const uint32_t* a, const uint32_t* b) {
    asm volatile(
        "mma.sync.aligned.m16n8k8.row.col.f32.tf32.tf32.f32 "
        "{%0,%1,%2,%3}, {%4,%5,%6,%7}, {%8,%9}, {%0,%1,%2,%3};\n"
        : "+f"(d[0]), "+f"(d[1]), "+f"(d[2]), "+f"(d[3])
        : "r"(a[0]), "r"(a[1]), "r"(a[2]), "r"(a[3]), "r"(b[0]), "r"(b[1]));
}
__device__ __forceinline__ float gelu_f(float v) {
    return 0.5f * v * (1.0f + erff(v * 0.70710678118654752f));
}
__device__ __forceinline__ float fexp(float x) {
    float y = x * 1.4426950408889634f;
    y = fmaxf(y, -126.0f);
    const float magic = 12582912.0f;
    const float z = y + magic;
    const int   n = __float_as_int(z) - 0x4B400000;
    const float f = y - (z - magic);
    float r = 0.0013333558f;
    r = fmaf(r, f, 0.0096181291f);
    r = fmaf(r, f, 0.0555041087f);
    r = fmaf(r, f, 0.2402265069f);
    r = fmaf(r, f, 0.6931471806f);
    r = fmaf(r, f, 1.0f);
    return __int_as_float(__float_as_int(r) + (n << 23));
}
__device__ __forceinline__ int permc(int x) {
    const int l = x & 7;
    return (x & 24) | ((l < 4) ? (l << 1) : (((l - 4) << 1) | 1));
}

// ---------------- weight prep ----------------------------------------------
__device__ void tp_tile(const float* __restrict__ src, float* __restrict__ dst,
                        int K, int N, int t)
{
    __shared__ float tbuf[32][33];
    const int tn = N >> 5;
    const int n0 = (t % tn) << 5, k0 = (t / tn) << 5;
    const int x = threadIdx.x & 31, y = threadIdx.x >> 5;
    #pragma unroll
    for (int i = 0; i < 32; i += 8)
        tbuf[y + i][x] = src[(size_t)(k0 + y + i) * N + n0 + x];
    __syncthreads();
    const int kp = k0 + permc(x);
    #pragma unroll
    for (int i = 0; i < 32; i += 8)
        dst[(size_t)(n0 + y + i) * K + kp] = to_tf32(tbuf[x][y + i]);
}

__global__ __launch_bounds__(256) void prep_a(
    const float* __restrict__ wq, const float* __restrict__ wk,
    const float* __restrict__ wv, const float* __restrict__ bq,
    const float* __restrict__ bk, const float* __restrict__ bv)
{
    const int blk = blockIdx.x;
    if (blk < 12288) {
        const int w = blk >> 12, t = blk & 4095;
        const float* src = (w == 0) ? wq : (w == 1) ? wk : wv;
        tp_tile(src, g_wqkvt + (size_t)w * 4194304, 2048, 2048, t);
    } else {
        const int idx = ((blk - 12288) << 8) + threadIdx.x;
        if (idx < 6144) {
            const int sel = idx >> 11;
            const float* b = (sel == 0) ? bq : (sel == 1) ? bk : bv;
            g_bqkv[idx] = b[idx & 2047];
        }
    }
}

__global__ __launch_bounds__(256) void prep_b(
    const float* __restrict__ wo, const float* __restrict__ w_in,
    const float* __restrict__ w_out)
{
    const int blk = blockIdx.x;
    if (blk < 4096)        tp_tile(wo,    g_wot,   2048, 2048, blk);
    else if (blk < 20480)  tp_tile(w_in,  g_wint,  2048, 8192, blk - 4096);
    else                   tp_tile(w_out, g_woutt, 8192, 2048, blk - 20480);
}

// ---------------- block reduce + LayerNorm ---------------------------------
__device__ __forceinline__ float block_sum256(float v) {
    __shared__ float red[8];
    #pragma unroll
    for (int o = 16; o; o >>= 1) v += __shfl_xor_sync(0xffffffffu, v, o);
    const int w = threadIdx.x >> 5, l = threadIdx.x & 31;
    __syncthreads();
    if (l == 0) red[w] = v;
    __syncthreads();
    float t = red[l & 7];
    t += __shfl_xor_sync(0xffffffffu, t, 1);
    t += __shfl_xor_sync(0xffffffffu, t, 2);
    t += __shfl_xor_sync(0xffffffffu, t, 4);
    return t;
}

__global__ __launch_bounds__(256) void ln_kernel(
    const float* __restrict__ x, const float* __restrict__ gw,
    const float* __restrict__ bw, float* __restrict__ y)
{
    const size_t base = (size_t)blockIdx.x * 2048;
    const int c0 = threadIdx.x << 3;
    const float4 v0 = *(const float4*)&x[base + c0];
    const float4 v1 = *(const float4*)&x[base + c0 + 4];

    float s = v0.x + v0.y + v0.z + v0.w + v1.x + v1.y + v1.z + v1.w;
    const float mean = block_sum256(s) * (1.0f / 2048.0f);

    float d[8];
    d[0] = v0.x - mean; d[1] = v0.y - mean; d[2] = v0.z - mean; d[3] = v0.w - mean;
    d[4] = v1.x - mean; d[5] = v1.y - mean; d[6] = v1.z - mean; d[7] = v1.w - mean;
    float q = 0.f;
    #pragma unroll
    for (int i = 0; i < 8; i++) q += d[i] * d[i];
    const float var = block_sum256(q) * (1.0f / 2048.0f);
    const float rs = rsqrtf(var + 1e-5f);

    const float4 g0 = *(const float4*)&gw[c0];
    const float4 g1 = *(const float4*)&gw[c0 + 4];
    const float4 b0 = *(const float4*)&bw[c0];
    const float4 b1 = *(const float4*)&bw[c0 + 4];
    const float ga[8] = {g0.x, g0.y, g0.z, g0.w, g1.x, g1.y, g1.z, g1.w};
    const float ba[8] = {b0.x, b0.y, b0.z, b0.w, b1.x, b1.y, b1.z, b1.w};

    float o[8];
    #pragma unroll
    for (int i = 0; i < 8; i++) o[i] = to_tf32(d[i] * rs * ga[i] + ba[i]);

    #pragma unroll
    for (int i = 0; i < 4; i++)
        *(float2*)&y[base + c0 + (i << 1)] = make_float2(o[i], o[i + 4]);
}

// ---------------- TF32 GEMM (unchanged from 3016us baseline) ---------------
#define GSMEM 98304

template<int ACT, int HASRES, int RND, int PERMC>
__global__ __launch_bounds__(256, 2) void gemm_cp(
    const float* __restrict__ A, const float* __restrict__ Wt,
    const float* __restrict__ bias, const float* __restrict__ res,
    float* __restrict__ C, int M, int N, int K)
{
    extern __shared__ float sm[];
    const uint32_t sb = smem_u32(sm);
    const int tid = threadIdx.x;
    const int warp = tid >> 5, lane = tid & 31;
    const int wm = warp >> 1, wn = warp & 1;
    const int g = lane >> 2, t4 = lane & 3;
    const int bm = blockIdx.y << 7, bn = blockIdx.x << 7;

    const float* Ab = A  + (size_t)bm * K;
    const float* Bb = Wt + (size_t)bn * K;
    const int KT = K >> 5;

    const int r0 = tid >> 3;
    const int cc = (tid & 7) << 2;
    const uint32_t dcol = (uint32_t)((cc ^ ((r0 & 3) << 3)) << 2);
    const float* ga[4]; const float* gb[4];
    uint32_t da[4], db[4];
    #pragma unroll
    for (int i = 0; i < 4; i++) {
        const int row = r0 + (i << 5);
        ga[i] = Ab + (size_t)row * K + cc;
        gb[i] = Bb + (size_t)row * K + cc;
        da[i] = (uint32_t)(row * 128) + dcol;
        db[i] = 16384u + (uint32_t)(row * 128) + dcol;
    }

    float acc[2][8][4];
    #pragma unroll
    for (int a = 0; a < 2; a++)
        #pragma unroll
        for (int b2 = 0; b2 < 8; b2++)
            #pragma unroll
            for (int c = 0; c < 4; c++) acc[a][b2][c] = 0.f;

    auto issue = [&](int s) {
        const uint32_t st = sb + (uint32_t)s * 32768u;
        #pragma unroll
        for (int i = 0; i < 4; i++) { cp16(st + da[i], ga[i]); ga[i] += 32; }
        #pragma unroll
        for (int i = 0; i < 4; i++) { cp16(st + db[i], gb[i]); gb[i] += 32; }
        asm volatile("cp.async.commit_group;" ::: "memory");
    };

    issue(0);
    issue(1);

    const int swz = (g & 3) << 3;
    int kcs[4];
    #pragma unroll
    for (int ks = 0; ks < 4; ks++) kcs[ks] = ((ks << 3) ^ swz) | (t4 << 1);

    int s = 0;
    for (int kt = 0; kt < KT; kt++) {
        if (kt + 1 < KT) asm volatile("cp.async.wait_group 1;" ::: "memory");
        else             asm volatile("cp.async.wait_group 0;" ::: "memory");
        __syncthreads();
        if (kt + 2 < KT) {
            int ns = s + 2; if (ns >= 3) ns -= 3;
            issue(ns);
        }
        const float* As = sm + s * 8192;
        const float* Bs = As + 4096;

        #pragma unroll
        for (int ks = 0; ks < 4; ks++) {
            const int kc = kcs[ks];
            uint32_t af[2][4];
            #pragma unroll
            for (int mi = 0; mi < 2; mi++) {
                const int mr = (wm << 5) + (mi << 4) + g;
                const float2 a02 = *(const float2*)&As[mr * 32 + kc];
                const float2 a13 = *(const float2*)&As[(mr + 8) * 32 + kc];
                af[mi][0] = __float_as_uint(a02.x);
                af[mi][1] = __float_as_uint(a13.x);
                af[mi][2] = __float_as_uint(a02.y);
                af[mi][3] = __float_as_uint(a13.y);
            }
            #pragma unroll
            for (int ni = 0; ni < 8; ni++) {
                const int nc = (wn << 6) + (ni << 3) + g;
                const float2 b01 = *(const float2*)&Bs[nc * 32 + kc];
                uint32_t bf[2];
                bf[0] = __float_as_uint(b01.x);
                bf[1] = __float_as_uint(b01.y);
                mma8(acc[0][ni], af[0], bf);
                mma8(acc[1][ni], af[1], bf);
            }
        }
        if (++s == 3) s = 0;
    }

    #pragma unroll
    for (int mi = 0; mi < 2; mi++) {
        const int row0 = bm + (wm << 5) + (mi << 4) + g;
        #pragma unroll
        for (int ni = 0; ni < 8; ni++) {
            const int base = bn + (wn << 6) + (ni << 3);
            const int lcol = base + (t4 << 1);
            const float b0 = bias[lcol], b1 = bias[lcol + 1];
            float v00 = acc[mi][ni][0] + b0, v01 = acc[mi][ni][1] + b1;
            float v10 = acc[mi][ni][2] + b0, v11 = acc[mi][ni][3] + b1;
            const size_t i0 = (size_t)row0 * N + lcol;
            const size_t i1 = i0 + (size_t)8 * N;
            if (HASRES) {
                v00 += res[i0]; v01 += res[i0 + 1];
                v10 += res[i1]; v11 += res[i1 + 1];
            }
            if (ACT == 1) {
                v00 = to_tf32(gelu_f(v00)); v01 = to_tf32(gelu_f(v01));
                v10 = to_tf32(gelu_f(v10)); v11 = to_tf32(gelu_f(v11));
            } else if (RND) {
                v00 = to_tf32(v00); v01 = to_tf32(v01);
                v10 = to_tf32(v10); v11 = to_tf32(v11);
            }
            if (PERMC) {
                const int p0 = (t4 < 2) ? (t4 << 2) : ((t4 << 2) - 7);
                const size_t r0i = (size_t)row0 * N + base;
                const size_t r1i = r0i + (size_t)8 * N;
                C[r0i + p0] = v00; C[r0i + p0 + 2] = v01;
                C[r1i + p0] = v10; C[r1i + p0 + 2] = v11;
            } else {
                *(float2*)&C[i0] = make_float2(v00, v01);
                *(float2*)&C[i1] = make_float2(v10, v11);
            }
        }
    }
}

// ---------------- causal flash attention: q-tile 128, 512 threads ----------
// smem floats: Qs[128][132]=16896 | Ks[64][132]=8448 | Vs[64][132]=8448 |
//              Ss[128][68]=8704 | m/l/a[128]x3 ; total 42880 f = 171520 B
#define FSMEM 171520

__global__ __launch_bounds__(512, 1) void flash_kernel(
    const float* __restrict__ QKV, float* __restrict__ O)
{
    extern __shared__ float smf[];
    float* Qs   = smf;                 // [128][132]
    float* Ks   = smf + 16896;         // [64][132]
    float* Vs   = smf + 25344;         // [64][132]
    float* Ss   = smf + 33792;         // [128][68]
    float* mrow = smf + 42496;
    float* lrow = smf + 42624;
    float* arow = smf + 42752;

    const int tid = threadIdx.x;
    const int warp = tid >> 5, lane = tid & 31;
    const int g = lane >> 2, t4 = lane & 3;
    const int wm = warp >> 2, wn = warp & 3;
    const int b = blockIdx.y >> 4, h = blockIdx.y & 15;
    const int qi = (int)gridDim.x - 1 - (int)blockIdx.x;   // heaviest first
    const int q0 = qi << 7;
    const size_t qbase = (size_t)b * 2048 * 6144 + (size_t)h * 128;
    const float* Qg = QKV + qbase;
    const float* Kg = QKV + qbase + 2048;
    const float* Vg = QKV + qbase + 4096;
    float*       Og = O + ((size_t)b * 2048) * 2048 + (size_t)h * 128;

    #pragma unroll
    for (int rr = 0; rr < 8; rr++) {
        const int f4 = tid + (rr << 9);
        const int row = f4 >> 5, c4 = f4 & 31;
        *(float4*)&Qs[row * 132 + (c4 << 2)] =
            *(const float4*)&Qg[(size_t)(q0 + row) * 6144 + (c4 << 2)];
    }
    if (tid < 128) { mrow[tid] = -1e30f; lrow[tid] = 0.f; }

    float o[2][4][4];
    #pragma unroll
    for (int mi = 0; mi < 2; mi++)
        #pragma unroll
        for (int ni = 0; ni < 4; ni++)
            #pragma unroll
            for (int c = 0; c < 4; c++) o[mi][ni][c] = 0.f;

    const int ntile = (qi << 1) + 2;
    for (int kt = 0; kt < ntile; kt++) {
        const int k0 = kt << 6;
        __syncthreads();
        #pragma unroll
        for (int rr = 0; rr < 4; rr++) {
            const int f4 = tid + (rr << 9);
            const int row = f4 >> 5, c4 = f4 & 31;
            *(float4*)&Ks[row * 132 + (c4 << 2)] =
                *(const float4*)&Kg[(size_t)(k0 + row) * 6144 + (c4 << 2)];
            *(float4*)&Vs[row * 132 + (c4 << 2)] =
                *(const float4*)&Vg[(size_t)(k0 + row) * 6144 + (c4 << 2)];
        }
        __syncthreads();

        // S[128,64] = Q K^T (warp tile 32q x 16n)
        {
            float sacc[2][2][4];
            #pragma unroll
            for (int mi = 0; mi < 2; mi++)
                #pragma unroll
                for (int ni = 0; ni < 2; ni++)
                    #pragma unroll
                    for (int c = 0; c < 4; c++) sacc[mi][ni][c] = 0.f;
            const int m0 = wm << 5, nb = wn << 4;
            #pragma unroll
            for (int kk = 0; kk < 16; kk++) {
                const int kb = kk << 3;
                uint32_t af[2][4];
                #pragma unroll
                for (int mi = 0; mi < 2; mi++) {
                    const int mr = m0 + (mi << 4);
                    af[mi][0] = __float_as_uint(Qs[(mr + g    ) * 132 + kb + t4    ]);
                    af[mi][1] = __float_as_uint(Qs[(mr + g + 8) * 132 + kb + t4    ]);
                    af[mi][2] = __float_as_uint(Qs[(mr + g    ) * 132 + kb + t4 + 4]);
                    af[mi][3] = __float_as_uint(Qs[(mr + g + 8) * 132 + kb + t4 + 4]);
                }
                #pragma unroll
                for (int ni = 0; ni < 2; ni++) {
                    const int n = nb + (ni << 3) + g;
                    uint32_t bf[2];
                    bf[0] = __float_as_uint(Ks[n * 132 + kb + t4    ]);
                    bf[1] = __float_as_uint(Ks[n * 132 + kb + t4 + 4]);
                    mma8(sacc[0][ni], af[0], bf);
                    mma8(sacc[1][ni], af[1], bf);
                }
            }
            #pragma unroll
            for (int mi = 0; mi < 2; mi++) {
                const int r0 = m0 + (mi << 4) + g, r1 = r0 + 8;
                #pragma unroll
                for (int ni = 0; ni < 2; ni++) {
                    const int col = nb + (ni << 3) + (t4 << 1);
                    float v00 = sacc[mi][ni][0] * 0.08838834764831845f;
                    float v01 = sacc[mi][ni][1] * 0.08838834764831845f;
                    float v10 = sacc[mi][ni][2] * 0.08838834764831845f;
                    float v11 = sacc[mi][ni][3] * 0.08838834764831845f;
                    if (k0 + col     > q0 + r0) v00 = -1e30f;
                    if (k0 + col + 1 > q0 + r0) v01 = -1e30f;
                    if (k0 + col     > q0 + r1) v10 = -1e30f;
                    if (k0 + col + 1 > q0 + r1) v11 = -1e30f;
                    Ss[r0 * 68 + col] = v00; Ss[r0 * 68 + col + 1] = v01;
                    Ss[r1 * 68 + col] = v10; Ss[r1 * 68 + col + 1] = v11;
                }
            }
        }
        __syncthreads();

        // online softmax: 128 rows, 4 thr/row; P tf32-rounded; poly exp
        {
            const int rid = tid >> 2, c0 = tid & 3;
            float mx = -1e30f;
            #pragma unroll
            for (int jc = c0; jc < 64; jc += 4) mx = fmaxf(mx, Ss[rid * 68 + jc]);
            mx = fmaxf(mx, __shfl_xor_sync(0xffffffffu, mx, 1));
            mx = fmaxf(mx, __shfl_xor_sync(0xffffffffu, mx, 2));
            const float mold = mrow[rid];
            const float mnew = fmaxf(mold, mx);
            float sum = 0.f;
            #pragma unroll
            for (int jc = c0; jc < 64; jc += 4) {
                const float p = to_tf32(fexp(Ss[rid * 68 + jc] - mnew));
                Ss[rid * 68 + jc] = p;
                sum += p;
            }
            sum += __shfl_xor_sync(0xffffffffu, sum, 1);
            sum += __shfl_xor_sync(0xffffffffu, sum, 2);
            if (c0 == 0) {
                arow[rid] = fexp(mold - mnew);
                lrow[rid] = lrow[rid] * arow[rid] + sum;
                mrow[rid] = mnew;
            }
        }
        __syncthreads();

        // O^T[128d,128q] += V^T @ P^T (warp tile 32d x 32q)
        {
            const int d0 = wm << 5, qw = wn << 5;
            #pragma unroll
            for (int ni = 0; ni < 4; ni++) {
                const int cq = qw + (ni << 3) + (t4 << 1);
                const float a0 = arow[cq], a1 = arow[cq + 1];
                #pragma unroll
                for (int mi = 0; mi < 2; mi++) {
                    o[mi][ni][0] *= a0; o[mi][ni][1] *= a1;
                    o[mi][ni][2] *= a0; o[mi][ni][3] *= a1;
                }
            }
            #pragma unroll
            for (int k_ = 0; k_ < 8; k_++) {
                const int kb = k_ << 3;
                uint32_t af[2][4];
                #pragma unroll
                for (int mi = 0; mi < 2; mi++) {
                    const int dm = d0 + (mi << 4);
                    af[mi][0] = __float_as_uint(Vs[(kb + t4    ) * 132 + dm + g    ]);
                    af[mi][1] = __float_as_uint(Vs[(kb + t4    ) * 132 + dm + g + 8]);
                    af[mi][2] = __float_as_uint(Vs[(kb + t4 + 4) * 132 + dm + g    ]);
                    af[mi][3] = __float_as_uint(Vs[(kb + t4 + 4) * 132 + dm + g + 8]);
                }
                #pragma unroll
                for (int ni = 0; ni < 4; ni++) {
                    const int nq = qw + (ni << 3) + g;
                    uint32_t bf[2];
                    bf[0] = __float_as_uint(Ss[nq * 68 + kb + t4    ]);
                    bf[1] = __float_as_uint(Ss[nq * 68 + kb + t4 + 4]);
                    mma8(o[0][ni], af[0], bf);
                    mma8(o[1][ni], af[1], bf);
                }
            }
        }
    }

    // normalize + store O[q][d], d-index k-permuted for oproj GEMM A
    __syncthreads();
    {
        const int d0 = wm << 5, qw = wn << 5;
        const int pg = (g < 4) ? (g << 1) : ((g << 1) - 7);
        #pragma unroll
        for (int ni = 0; ni < 4; ni++) {
            const int cq = qw + (ni << 3) + (t4 << 1);
            const float inv0 = 1.0f / lrow[cq], inv1 = 1.0f / lrow[cq + 1];
            #pragma unroll
            for (int mi = 0; mi < 2; mi++) {
                const int db = d0 + (mi << 4);
                Og[(size_t)(q0 + cq    ) * 2048 + db + pg    ] = to_tf32(o[mi][ni][0] * inv0);
                Og[(size_t)(q0 + cq + 1) * 2048 + db + pg    ] = to_tf32(o[mi][ni][1] * inv1);
                Og[(size_t)(q0 + cq    ) * 2048 + db + 8 + pg] = to_tf32(o[mi][ni][2] * inv0);
                Og[(size_t)(q0 + cq + 1) * 2048 + db + 8 + pg] = to_tf32(o[mi][ni][3] * inv1);
            }
        }
    }
}

// ---------------- host orchestration ---------------------------------------
extern "C" void kernel_launch(void* const* d_in, const int* in_sizes, int n_in,
                              void* d_out, int out_size)
{
    const float* x     = (const float*)d_in[0];
    const float* ln1_g = (const float*)d_in[2];
    const float* ln1_b = (const float*)d_in[3];
    const float* wq    = (const float*)d_in[4];
    const float* bq    = (const float*)d_in[5];
    const float* wk    = (const float*)d_in[6];
    const float* bk    = (const float*)d_in[7];
    const float* wv    = (const float*)d_in[8];
    const float* bv    = (const float*)d_in[9];
    const float* wo    = (const float*)d_in[10];
    const float* bo    = (const float*)d_in[11];
    const float* ln2_g = (const float*)d_in[12];
    const float* ln2_b = (const float*)d_in[13];
    const float* w_in  = (const float*)d_in[14];
    const float* b_in  = (const float*)d_in[15];
    const float* w_out = (const float*)d_in[16];
    const float* b_out = (const float*)d_in[17];
    float* out = (float*)d_out;

    float *xn, *qkv, *attn, *x1, *h, *wqkvt, *wot, *wint, *woutt, *bqkv;
    cudaGetSymbolAddress((void**)&xn,     g_xn);
    cudaGetSymbolAddress((void**)&qkv,    g_qkv);
    cudaGetSymbolAddress((void**)&attn,   g_attn);
    cudaGetSymbolAddress((void**)&x1,     g_x1);
    cudaGetSymbolAddress((void**)&h,      g_h);
    cudaGetSymbolAddress((void**)&wqkvt,  g_wqkvt);
    cudaGetSymbolAddress((void**)&wot,    g_wot);
    cudaGetSymbolAddress((void**)&wint,   g_wint);
    cudaGetSymbolAddress((void**)&woutt,  g_woutt);
    cudaGetSymbolAddress((void**)&bqkv,   g_bqkv);

    cudaFuncSetAttribute(flash_kernel,
                         cudaFuncAttributeMaxDynamicSharedMemorySize, FSMEM);
    cudaFuncSetAttribute(gemm_cp<0,0,1,0>,
                         cudaFuncAttributeMaxDynamicSharedMemorySize, GSMEM);
    cudaFuncSetAttribute(gemm_cp<0,1,0,0>,
                         cudaFuncAttributeMaxDynamicSharedMemorySize, GSMEM);
    cudaFuncSetAttribute(gemm_cp<1,0,0,1>,
                         cudaFuncAttributeMaxDynamicSharedMemorySize, GSMEM);

    prep_a<<<12312, 256>>>(wq, wk, wv, bq, bk, bv);                     // 1
    prep_b<<<36864, 256>>>(wo, w_in, w_out);                            // 2
    ln_kernel<<<4096, 256>>>(x, ln1_g, ln1_b, xn);                      // 3
    gemm_cp<0,0,1,0><<<dim3(48, 32), 256, GSMEM>>>(                     // 4: QKV
        xn, wqkvt, bqkv, nullptr, qkv, 4096, 6144, 2048);
    flash_kernel<<<dim3(16, 32), 512, FSMEM>>>(qkv, attn);              // 5
    gemm_cp<0,1,0,0><<<dim3(16, 32), 256, GSMEM>>>(                     // 6: O-proj
        attn, wot, bo, x, x1, 4096, 2048, 2048);
    ln_kernel<<<4096, 256>>>(x1, ln2_g, ln2_b, xn);                     // 7
    gemm_cp<1,0,0,1><<<dim3(64, 32), 256, GSMEM>>>(                     // 8: MLP in
        xn, wint, b_in, nullptr, h, 4096, 8192, 2048);
    gemm_cp<0,1,0,0><<<dim3(16, 32), 256, GSMEM>>>(                     // 9: MLP out
        h, woutt, b_out, x1, out, 4096, 2048, 8192);
}